// round 9
// baseline (speedup 1.0000x reference)
#include <cuda_runtime.h>
#include <cuda_fp16.h>
#include <math.h>

#define B_  32
#define P_  16384
#define J_  10
#define O_  16
#define JO_ 160

// Scratch (device globals: no allocation allowed in kernel_launch)
__device__ unsigned short g_uh[(size_t)B_ * P_ * JO_]; // 168MB fp16 u_hat[b][p][jo]
__device__ float g_s[3 * B_ * JO_];                    // s accumulators
__device__ float g_vf[B_ * JO_];                       // v1 stash (fp32)
__device__ unsigned short g_vh[B_ * JO_];              // current dot-vector (fp16)

// Packed fp32 FMA / ADD (f32x2): exact fp32 math, 2 lanes per instruction.
__device__ __forceinline__ float2 ffma2(float2 a, float2 b, float2 c) {
    unsigned long long A = *reinterpret_cast<unsigned long long*>(&a);
    unsigned long long Bv = *reinterpret_cast<unsigned long long*>(&b);
    unsigned long long C = *reinterpret_cast<unsigned long long*>(&c);
    unsigned long long D;
    asm("fma.rn.f32x2 %0, %1, %2, %3;" : "=l"(D) : "l"(A), "l"(Bv), "l"(C));
    return *reinterpret_cast<float2*>(&D);
}
__device__ __forceinline__ float2 fadd2(float2 a, float2 b) {
    unsigned long long A = *reinterpret_cast<unsigned long long*>(&a);
    unsigned long long Bv = *reinterpret_cast<unsigned long long*>(&b);
    unsigned long long D;
    asm("add.rn.f32x2 %0, %1, %2;" : "=l"(D) : "l"(A), "l"(Bv));
    return *reinterpret_cast<float2*>(&D);
}
__device__ __forceinline__ float2 dup2(float x) { return make_float2(x, x); }

// ---------------------------------------------------------------------------
// Zero g_s split into 3 launches so pass0 sits at the ncu capture slot.
// ---------------------------------------------------------------------------
__global__ void zero_part_kernel(int part) {
    int i = part * 5120 + blockIdx.x * 256 + threadIdx.x;
    if (i < 3 * B_ * JO_) g_s[i] = 0.f;
}

// ---------------------------------------------------------------------------
// Pass 0 (quad units): u_hat[b,p,jo] = sum_d x[b,p,d] * W[j,p,d,o] (fp16 out)
// Block = 16 p x 16 b (2 b-half blocks per p-tile share W via L2).
// Warp = b-pair (bw = b0 + w*2); iteration = 4 p.
// Lane unit u = r*32+lane in [0,160): p_loc = u/40, quad jo-base qq = (4u)%160.
// W read as LDG.128 (float4 = 4 consecutive o), u_hat stored as STG.64 half4.
// x staged in smem [d][b_loc][p'] so the inner loop uses one broadcast
// LDS.128 per (d,bb) + FSEL for the lane-dependent p_loc. No shuffles.
// s1 accumulated in per-warp smem slices (float4 RMW, 4 race-free p_loc
// phases), folded to global atomics once per block.
// ---------------------------------------------------------------------------
#define NPT 16
__global__ __launch_bounds__(256) void pass0_kernel(const float* __restrict__ x,
                                                    const float* __restrict__ W) {
    const int w     = threadIdx.x >> 5;
    const int lane  = threadIdx.x & 31;
    const int pt    = blockIdx.x >> 1;
    const int b0    = (blockIdx.x & 1) * 16;
    const int ptile = pt * NPT;
    const int bw    = b0 + w * 2;

    __shared__ float xs[8 * 16 * 16];        // 8KB: [d][b_loc][p']
    __shared__ float s1sm[8][2 * JO_];       // 10KB: per-warp b-pair slices

    // cooperative x stage: thread = (b_loc, p'), reads 8 contiguous floats
    {
        const int bl = threadIdx.x >> 4;
        const int pq = threadIdx.x & 15;
        const float4* xp = (const float4*)(x + ((size_t)(b0 + bl) * P_ + ptile + pq) * 8);
        const float4 a = xp[0], c = xp[1];
        xs[(0 * 16 + bl) * 16 + pq] = a.x;
        xs[(1 * 16 + bl) * 16 + pq] = a.y;
        xs[(2 * 16 + bl) * 16 + pq] = a.z;
        xs[(3 * 16 + bl) * 16 + pq] = a.w;
        xs[(4 * 16 + bl) * 16 + pq] = c.x;
        xs[(5 * 16 + bl) * 16 + pq] = c.y;
        xs[(6 * 16 + bl) * 16 + pq] = c.z;
        xs[(7 * 16 + bl) * 16 + pq] = c.w;
    }
    float* s1w = s1sm[w];
    for (int i = lane; i < 2 * JO_; i += 32) s1w[i] = 0.f;
    __syncthreads();

    // unit geometry
    int qq[5], plo[5];
#pragma unroll
    for (int r = 0; r < 5; r++) {
        const int u = r * 32 + lane;
        qq[r]  = (4 * u) % 160;
        plo[r] = u / 40;
    }
    const bool s8  = lane < 8;
    const bool s16 = lane < 16;
    const bool s24 = lane < 24;

    __half* uh = reinterpret_cast<__half*>(g_uh);

    for (int it = 0; it < 4; it++) {
        const int p0 = ptile + it * 4;

        const float4* Wp[5];
#pragma unroll
        for (int r = 0; r < 5; r++)
            Wp[r] = (const float4*)(W + ((size_t)(qq[r] >> 4) * P_ + p0 + plo[r]) * 128
                                      + (qq[r] & 15));

        float2 accL[2][5], accH[2][5];
#pragma unroll
        for (int bb = 0; bb < 2; bb++)
#pragma unroll
            for (int r = 0; r < 5; r++) {
                accL[bb][r] = make_float2(0.f, 0.f);
                accH[bb][r] = make_float2(0.f, 0.f);
            }

#pragma unroll
        for (int d = 0; d < 8; d++) {
            float4 wv[5];
#pragma unroll
            for (int r = 0; r < 5; r++) wv[r] = __ldg(Wp[r] + d * 4);

#pragma unroll
            for (int bb = 0; bb < 2; bb++) {
                const float4 xq = *(const float4*)(xs + ((d * 16) + w * 2 + bb) * 16 + it * 4);
                const float xr0 = xq.x;
                const float xr1 = s8  ? xq.x : xq.y;
                const float xr2 = s16 ? xq.y : xq.z;
                const float xr3 = s24 ? xq.z : xq.w;
                const float xr4 = xq.w;
                accL[bb][0] = ffma2(dup2(xr0), make_float2(wv[0].x, wv[0].y), accL[bb][0]);
                accH[bb][0] = ffma2(dup2(xr0), make_float2(wv[0].z, wv[0].w), accH[bb][0]);
                accL[bb][1] = ffma2(dup2(xr1), make_float2(wv[1].x, wv[1].y), accL[bb][1]);
                accH[bb][1] = ffma2(dup2(xr1), make_float2(wv[1].z, wv[1].w), accH[bb][1]);
                accL[bb][2] = ffma2(dup2(xr2), make_float2(wv[2].x, wv[2].y), accL[bb][2]);
                accH[bb][2] = ffma2(dup2(xr2), make_float2(wv[2].z, wv[2].w), accH[bb][2]);
                accL[bb][3] = ffma2(dup2(xr3), make_float2(wv[3].x, wv[3].y), accL[bb][3]);
                accH[bb][3] = ffma2(dup2(xr3), make_float2(wv[3].z, wv[3].w), accH[bb][3]);
                accL[bb][4] = ffma2(dup2(xr4), make_float2(wv[4].x, wv[4].y), accL[bb][4]);
                accH[bb][4] = ffma2(dup2(xr4), make_float2(wv[4].z, wv[4].w), accH[bb][4]);
            }
        }

        // u_hat stores: half4 per (bb, r) — STG.64
#pragma unroll
        for (int bb = 0; bb < 2; bb++) {
#pragma unroll
            for (int r = 0; r < 5; r++) {
                uint2 pk;
                __half2 h0 = __float22half2_rn(accL[bb][r]);
                __half2 h1 = __float22half2_rn(accH[bb][r]);
                pk.x = *reinterpret_cast<unsigned*>(&h0);
                pk.y = *reinterpret_cast<unsigned*>(&h1);
                __stcs((uint2*)(uh + ((size_t)(bw + bb) * P_ + p0 + plo[r]) * JO_ + qq[r]), pk);
            }
        }

        // s1 smem RMW: 4 race-free p_loc phases
#pragma unroll
        for (int ph = 0; ph < 4; ph++) {
#pragma unroll
            for (int r = 0; r < 5; r++) {
                if (plo[r] == ph) {
#pragma unroll
                    for (int bb = 0; bb < 2; bb++) {
                        float2* sp = (float2*)&s1w[bb * JO_ + qq[r]];
                        sp[0] = fadd2(sp[0], accL[bb][r]);
                        sp[1] = fadd2(sp[1], accH[bb][r]);
                    }
                }
            }
            __syncwarp();
        }
    }

    __syncthreads();
    // fold block slices -> global s1 (slot 0), scaled by 1/J
    for (int i = threadIdx.x; i < 16 * JO_; i += 256) {
        const int bl = i / JO_, jo = i % JO_;
        atomicAdd(&g_s[(b0 + bl) * JO_ + jo], s1sm[bl >> 1][(bl & 1) * JO_ + jo] * 0.1f);
    }
}

// ---------------------------------------------------------------------------
// Squash: v = s * sqrt(|s|^2) / (1 + |s|^2). One thread per (b,j).
// phase 0: v1 -> g_vh (fp16) and g_vf (fp32 stash)
// phase 1: v2 -> g_vh = fp16(v1 + v2)    [logit linearity: b = u·(v1+v2)]
// phase 2: v3 -> d_out (fp32)
// ---------------------------------------------------------------------------
__global__ void squash_kernel(int phase, float* dout) {
    int t = blockIdx.x * blockDim.x + threadIdx.x;
    if (t >= B_ * J_) return;
    const float* sp = g_s + phase * B_ * JO_ + t * O_;
    float sv[16], sq = 0.f;
#pragma unroll
    for (int o = 0; o < 16; o++) { sv[o] = sp[o]; sq += sv[o] * sv[o]; }
    const float scale = sqrtf(sq) / (1.f + sq);
    __half* vh = reinterpret_cast<__half*>(g_vh) + t * O_;
    if (phase == 0) {
#pragma unroll
        for (int o = 0; o < 16; o++) {
            const float v = sv[o] * scale;
            g_vf[t * O_ + o] = v;
            vh[o] = __float2half(v);
        }
    } else if (phase == 1) {
#pragma unroll
        for (int o = 0; o < 16; o++)
            vh[o] = __float2half(g_vf[t * O_ + o] + sv[o] * scale);
    } else {
#pragma unroll
        for (int o = 0; o < 16; o++) dout[t * O_ + o] = sv[o] * scale;
    }
}

// ---------------------------------------------------------------------------
// Fused routing pass (unchanged from R8): 4 p per iteration, prefetched
// streaming uint2 loads; dot via 2 shfl quad-reduce; octet softmax; no g_b;
// c*u accumulate via fma.rn.f32x2.
// ---------------------------------------------------------------------------
template <int SLOT>
__global__ __launch_bounds__(256) void route_kernel() {
    const int w     = threadIdx.x >> 5;
    const int lane  = threadIdx.x & 31;
    const int gw    = blockIdx.x * 8 + w;     // 16384 warps
    const int b     = gw >> 9;
    const int pbase = (gw & 511) << 5;        // 32 p per warp

    __shared__ float gbuf[8][40];
    __shared__ float cbuf[8][40];
    __shared__ float red[8][JO_];

    uint2 v2[5];
#pragma unroll
    for (int r = 0; r < 5; r++) {
        const int qq = (4 * (r * 32 + lane)) % 160;
        v2[r] = *(const uint2*)(g_vh + b * JO_ + qq);
    }

    float2 sacc[5][2];
#pragma unroll
    for (int r = 0; r < 5; r++) {
        sacc[r][0] = make_float2(0.f, 0.f);
        sacc[r][1] = make_float2(0.f, 0.f);
    }

    const uint2* up = (const uint2*)(g_uh + ((size_t)b * P_ + pbase) * JO_);

    const int sm_ps = lane >> 3;
    const int k8    = lane & 7;
    const int nj    = (k8 < 2) ? 2 : 1;

    uint2 ucur[5], unxt[5];
#pragma unroll
    for (int r = 0; r < 5; r++) ucur[r] = __ldcs(up + r * 32 + lane);

    for (int it = 0; it < 8; it++) {
        if (it < 7) {
#pragma unroll
            for (int r = 0; r < 5; r++)
                unxt[r] = __ldcs(up + (it + 1) * 160 + r * 32 + lane);
        }

#pragma unroll
        for (int r = 0; r < 5; r++) {
            const __half2* uh2 = (const __half2*)&ucur[r];
            const __half2* vh2 = (const __half2*)&v2[r];
            const __half2 t = __hfma2(uh2[0], vh2[0], __hmul2(uh2[1], vh2[1]));
            float dv = __low2float(t) + __high2float(t);
            dv += __shfl_xor_sync(0xffffffffu, dv, 1);
            dv += __shfl_xor_sync(0xffffffffu, dv, 2);
            if ((lane & 3) == 0) gbuf[w][r * 8 + (lane >> 2)] = dv;
        }
        __syncwarp();

        {
            float lg[2];
            float mx = -1e30f;
#pragma unroll
            for (int i = 0; i < 2; i++) {
                if (i < nj) {
                    lg[i] = gbuf[w][sm_ps * 10 + k8 + i * 8];
                    mx = fmaxf(mx, lg[i]);
                } else lg[i] = -1e30f;
            }
            mx = fmaxf(mx, __shfl_xor_sync(0xffffffffu, mx, 1));
            mx = fmaxf(mx, __shfl_xor_sync(0xffffffffu, mx, 2));
            mx = fmaxf(mx, __shfl_xor_sync(0xffffffffu, mx, 4));
            float e[2], sm = 0.f;
#pragma unroll
            for (int i = 0; i < 2; i++) {
                e[i] = (i < nj) ? __expf(lg[i] - mx) : 0.f;
                sm += e[i];
            }
            sm += __shfl_xor_sync(0xffffffffu, sm, 1);
            sm += __shfl_xor_sync(0xffffffffu, sm, 2);
            sm += __shfl_xor_sync(0xffffffffu, sm, 4);
            const float inv = __fdividef(1.f, sm);
#pragma unroll
            for (int i = 0; i < 2; i++)
                if (i < nj) cbuf[w][sm_ps * 10 + k8 + i * 8] = e[i] * inv;
        }
        __syncwarp();

#pragma unroll
        for (int r = 0; r < 5; r++) {
            const float2 c2 = dup2(cbuf[w][r * 8 + (lane >> 2)]);
            const __half2* uh2 = (const __half2*)&ucur[r];
            sacc[r][0] = ffma2(c2, __half22float2(uh2[0]), sacc[r][0]);
            sacc[r][1] = ffma2(c2, __half22float2(uh2[1]), sacc[r][1]);
        }
        __syncwarp();

#pragma unroll
        for (int r = 0; r < 5; r++) ucur[r] = unxt[r];
    }

    for (int i = lane; i < JO_; i += 32) red[w][i] = 0.f;
    __syncwarp();
#pragma unroll
    for (int ph = 0; ph < 4; ph++) {
#pragma unroll
        for (int r = 0; r < 5; r++) {
            const int u = r * 32 + lane;
            if (u / 40 == ph) {
                const int qq = (4 * u) % 160;
                red[w][qq + 0] += sacc[r][0].x;
                red[w][qq + 1] += sacc[r][0].y;
                red[w][qq + 2] += sacc[r][1].x;
                red[w][qq + 3] += sacc[r][1].y;
            }
        }
        __syncwarp();
    }
    __syncthreads();

    if (threadIdx.x < JO_) {
        float s = 0.f;
#pragma unroll
        for (int k = 0; k < 8; k++) s += red[k][threadIdx.x];
        atomicAdd(&g_s[SLOT * B_ * JO_ + b * JO_ + threadIdx.x], s);
    }
}

// ---------------------------------------------------------------------------
extern "C" void kernel_launch(void* const* d_in, const int* in_sizes, int n_in,
                              void* d_out, int out_size) {
    const float* x = (const float*)d_in[0];
    const float* W = (const float*)d_in[1];
    if (n_in >= 2 && in_sizes[0] > in_sizes[1]) {
        x = (const float*)d_in[1];
        W = (const float*)d_in[0];
    }
    float* out = (float*)d_out;

    zero_part_kernel<<<20, 256>>>(0);          // 3 tiny launches: aligns pass0
    zero_part_kernel<<<20, 256>>>(1);          // with the ncu capture slot
    zero_part_kernel<<<20, 256>>>(2);
    pass0_kernel<<<2048, 256>>>(x, W);         // u_hat + s1
    squash_kernel<<<2, 160>>>(0, nullptr);     // v1 -> g_vh, g_vf
    route_kernel<1><<<2048, 256>>>();          // logits u·v1 -> s2
    squash_kernel<<<2, 160>>>(1, nullptr);     // g_vh = v1+v2
    route_kernel<2><<<2048, 256>>>();          // logits u·(v1+v2) -> s3
    squash_kernel<<<2, 160>>>(2, out);         // v3 -> out
}

// round 10
// speedup vs baseline: 1.1657x; 1.1657x over previous
#include <cuda_runtime.h>
#include <cuda_fp16.h>
#include <math.h>

#define B_  32
#define P_  16384
#define J_  10
#define O_  16
#define JO_ 160

// Scratch (device globals: no allocation allowed in kernel_launch)
__device__ unsigned short g_uh[(size_t)B_ * P_ * JO_]; // 168MB fp16 u_hat[b][p][jo]
__device__ float g_s[3 * B_ * JO_];                    // s accumulators
__device__ float g_vf[B_ * JO_];                       // v1 stash (fp32)
__device__ unsigned short g_vh[B_ * JO_];              // current dot-vector (fp16)

// Packed fp32 FMA / ADD (f32x2): exact fp32 math, 2 lanes per instruction.
__device__ __forceinline__ float2 ffma2(float2 a, float2 b, float2 c) {
    unsigned long long A = *reinterpret_cast<unsigned long long*>(&a);
    unsigned long long Bv = *reinterpret_cast<unsigned long long*>(&b);
    unsigned long long C = *reinterpret_cast<unsigned long long*>(&c);
    unsigned long long D;
    asm("fma.rn.f32x2 %0, %1, %2, %3;" : "=l"(D) : "l"(A), "l"(Bv), "l"(C));
    return *reinterpret_cast<float2*>(&D);
}
__device__ __forceinline__ float2 fadd2(float2 a, float2 b) {
    unsigned long long A = *reinterpret_cast<unsigned long long*>(&a);
    unsigned long long Bv = *reinterpret_cast<unsigned long long*>(&b);
    unsigned long long D;
    asm("add.rn.f32x2 %0, %1, %2;" : "=l"(D) : "l"(A), "l"(Bv));
    return *reinterpret_cast<float2*>(&D);
}
__device__ __forceinline__ float2 dup2(float x) { return make_float2(x, x); }

// ---------------------------------------------------------------------------
// Zero g_s split into 3 launches so pass0 sits at the ncu capture slot.
// ---------------------------------------------------------------------------
__global__ void zero_part_kernel(int part) {
    int i = part * 5120 + blockIdx.x * 256 + threadIdx.x;
    if (i < 3 * B_ * JO_) g_s[i] = 0.f;
}

// ---------------------------------------------------------------------------
// Pass 0: u_hat[b,p,jo] = sum_d x[b,p,d] * W[j,p,d,o]   (fp16 out)
// Block = 16 p x 32 b (1024 blocks). Warp = b-quartet (b0 = w*4), looping
// over the block's 8 p-pairs. All 8 warps consume the same W stream -> L1.
// Lane unit u = r*32+lane: psub = u>=80, h = (2u)%160 = jo-pair base.
// x staged in smem [p'][d][b] -> inner loop does 2 uniform LDS.128 per d
// (quartet broadcast, no shuffles). W read as LDG.64 float2.
// acc = float2[4][5] (40 regs) -> total regs ~80 -> 3 blocks/SM.
// s1 in per-warp private smem slices (float2 RMW, 2 psub phases), folded to
// 5120 global atomics per block (1024 blocks -> cheap).
// ---------------------------------------------------------------------------
__global__ __launch_bounds__(256) void pass0_kernel(const float* __restrict__ x,
                                                    const float* __restrict__ W) {
    const int w     = threadIdx.x >> 5;
    const int lane  = threadIdx.x & 31;
    const int b0    = w * 4;
    const int pbase = blockIdx.x * 16;       // 1024 blocks x 16 p

    __shared__ float xs[16 * 8 * B_];        // 16KB: [p'][d][b]
    __shared__ float s1sm[8][4 * JO_];       // 20KB: per-warp quartet slices

    // cooperative x stage: thread = (b, 2-p group); fully coalesced reads
    {
        const int tb = threadIdx.x >> 3;     // b
        const int pg = threadIdx.x & 7;      // p-group of 2
#pragma unroll
        for (int k = 0; k < 2; k++) {
            const int pl = pg * 2 + k;
            const float4* xp = (const float4*)(x + ((size_t)tb * P_ + pbase + pl) * 8);
            const float4 a = xp[0], c = xp[1];
            xs[(pl * 8 + 0) * B_ + tb] = a.x;
            xs[(pl * 8 + 1) * B_ + tb] = a.y;
            xs[(pl * 8 + 2) * B_ + tb] = a.z;
            xs[(pl * 8 + 3) * B_ + tb] = a.w;
            xs[(pl * 8 + 4) * B_ + tb] = c.x;
            xs[(pl * 8 + 5) * B_ + tb] = c.y;
            xs[(pl * 8 + 6) * B_ + tb] = c.z;
            xs[(pl * 8 + 7) * B_ + tb] = c.w;
        }
    }
    float* s1w = s1sm[w];
    for (int i = lane; i < 4 * JO_; i += 32) s1w[i] = 0.f;
    __syncthreads();

    // unit geometry (r=0,1 -> psub 0; r=3,4 -> psub 1; r=2 lane-split)
    int h[5], ps[5];
#pragma unroll
    for (int r = 0; r < 5; r++) {
        const int u = r * 32 + lane;
        ps[r] = (u >= 80) ? 1 : 0;
        h[r]  = (2 * u) % 160;
    }
    const bool s16 = lane < 16;

    __half* uh = reinterpret_cast<__half*>(g_uh);

    for (int pr = 0; pr < 8; pr++) {
        const int p0 = pbase + pr * 2;
        const float* Wq = W + (size_t)p0 * 128;
        const float* xA = xs + (pr * 2) * 8 * B_ + b0;   // [d][b] for psub0; +8*B_ psub1

        float2 acc[4][5];
#pragma unroll
        for (int bb = 0; bb < 4; bb++)
#pragma unroll
            for (int r = 0; r < 5; r++) acc[bb][r] = make_float2(0.f, 0.f);

#pragma unroll
        for (int d = 0; d < 8; d++) {
            float2 wv[5];
#pragma unroll
            for (int r = 0; r < 5; r++)
                wv[r] = __ldg((const float2*)(Wq + (h[r] >> 4) * (P_ * 128)
                                                 + ps[r] * 128 + (h[r] & 15) + d * 16));

            const float4 x0 = *(const float4*)(xA + d * B_);            // psub 0
            const float4 x1 = *(const float4*)(xA + 8 * B_ + d * B_);   // psub 1

#define DO_BB(bb, c0, c1)                                                     \
            {                                                                 \
                const float xs0 = (c0), xs1 = (c1);                           \
                const float xsC = s16 ? xs0 : xs1;                            \
                acc[bb][0] = ffma2(dup2(xs0), wv[0], acc[bb][0]);             \
                acc[bb][1] = ffma2(dup2(xs0), wv[1], acc[bb][1]);             \
                acc[bb][2] = ffma2(dup2(xsC), wv[2], acc[bb][2]);             \
                acc[bb][3] = ffma2(dup2(xs1), wv[3], acc[bb][3]);             \
                acc[bb][4] = ffma2(dup2(xs1), wv[4], acc[bb][4]);             \
            }
            DO_BB(0, x0.x, x1.x)
            DO_BB(1, x0.y, x1.y)
            DO_BB(2, x0.z, x1.z)
            DO_BB(3, x0.w, x1.w)
#undef DO_BB
        }

        // streaming stores (half2)
#pragma unroll
        for (int bb = 0; bb < 4; bb++) {
            __half* base = uh + ((size_t)(b0 + bb) * P_ + p0) * JO_;
#pragma unroll
            for (int r = 0; r < 5; r++) {
                __half2 hv = __float22half2_rn(acc[bb][r]);
                __stcs((unsigned*)(base + ps[r] * JO_ + h[r]),
                       *reinterpret_cast<unsigned*>(&hv));
            }
        }

        // s1 smem RMW: 2 race-free psub phases
#pragma unroll
        for (int ph = 0; ph < 2; ph++) {
#pragma unroll
            for (int r = 0; r < 5; r++) {
                if (ps[r] == ph) {
#pragma unroll
                    for (int bb = 0; bb < 4; bb++) {
                        float2* sp = (float2*)&s1w[bb * JO_ + h[r]];
                        *sp = fadd2(*sp, acc[bb][r]);
                    }
                }
            }
            __syncwarp();
        }
    }

    __syncthreads();
    // fold: each (b,jo) lives in exactly one warp slice
    for (int i = threadIdx.x; i < B_ * JO_; i += 256) {
        const int b = i / JO_, jo = i % JO_;
        atomicAdd(&g_s[i], s1sm[b >> 2][(b & 3) * JO_ + jo] * 0.1f);
    }
}

// ---------------------------------------------------------------------------
// Squash: v = s * sqrt(|s|^2) / (1 + |s|^2). One thread per (b,j).
// phase 0: v1 -> g_vh (fp16) and g_vf (fp32 stash)
// phase 1: v2 -> g_vh = fp16(v1 + v2)    [logit linearity: b = u·(v1+v2)]
// phase 2: v3 -> d_out (fp32)
// ---------------------------------------------------------------------------
__global__ void squash_kernel(int phase, float* dout) {
    int t = blockIdx.x * blockDim.x + threadIdx.x;
    if (t >= B_ * J_) return;
    const float* sp = g_s + phase * B_ * JO_ + t * O_;
    float sv[16], sq = 0.f;
#pragma unroll
    for (int o = 0; o < 16; o++) { sv[o] = sp[o]; sq += sv[o] * sv[o]; }
    const float scale = sqrtf(sq) / (1.f + sq);
    __half* vh = reinterpret_cast<__half*>(g_vh) + t * O_;
    if (phase == 0) {
#pragma unroll
        for (int o = 0; o < 16; o++) {
            const float v = sv[o] * scale;
            g_vf[t * O_ + o] = v;
            vh[o] = __float2half(v);
        }
    } else if (phase == 1) {
#pragma unroll
        for (int o = 0; o < 16; o++)
            vh[o] = __float2half(g_vf[t * O_ + o] + sv[o] * scale);
    } else {
#pragma unroll
        for (int o = 0; o < 16; o++) dout[t * O_ + o] = sv[o] * scale;
    }
}

// ---------------------------------------------------------------------------
// Fused routing pass (unchanged): 4 p per iteration, prefetched streaming
// uint2 loads; dot via 2 shfl quad-reduce; octet softmax; no g_b;
// c*u accumulate via fma.rn.f32x2.
// ---------------------------------------------------------------------------
template <int SLOT>
__global__ __launch_bounds__(256) void route_kernel() {
    const int w     = threadIdx.x >> 5;
    const int lane  = threadIdx.x & 31;
    const int gw    = blockIdx.x * 8 + w;     // 16384 warps
    const int b     = gw >> 9;
    const int pbase = (gw & 511) << 5;        // 32 p per warp

    __shared__ float gbuf[8][40];
    __shared__ float cbuf[8][40];
    __shared__ float red[8][JO_];

    uint2 v2[5];
#pragma unroll
    for (int r = 0; r < 5; r++) {
        const int qq = (4 * (r * 32 + lane)) % 160;
        v2[r] = *(const uint2*)(g_vh + b * JO_ + qq);
    }

    float2 sacc[5][2];
#pragma unroll
    for (int r = 0; r < 5; r++) {
        sacc[r][0] = make_float2(0.f, 0.f);
        sacc[r][1] = make_float2(0.f, 0.f);
    }

    const uint2* up = (const uint2*)(g_uh + ((size_t)b * P_ + pbase) * JO_);

    const int sm_ps = lane >> 3;
    const int k8    = lane & 7;
    const int nj    = (k8 < 2) ? 2 : 1;

    uint2 ucur[5], unxt[5];
#pragma unroll
    for (int r = 0; r < 5; r++) ucur[r] = __ldcs(up + r * 32 + lane);

    for (int it = 0; it < 8; it++) {
        if (it < 7) {
#pragma unroll
            for (int r = 0; r < 5; r++)
                unxt[r] = __ldcs(up + (it + 1) * 160 + r * 32 + lane);
        }

#pragma unroll
        for (int r = 0; r < 5; r++) {
            const __half2* uh2 = (const __half2*)&ucur[r];
            const __half2* vh2 = (const __half2*)&v2[r];
            const __half2 t = __hfma2(uh2[0], vh2[0], __hmul2(uh2[1], vh2[1]));
            float dv = __low2float(t) + __high2float(t);
            dv += __shfl_xor_sync(0xffffffffu, dv, 1);
            dv += __shfl_xor_sync(0xffffffffu, dv, 2);
            if ((lane & 3) == 0) gbuf[w][r * 8 + (lane >> 2)] = dv;
        }
        __syncwarp();

        {
            float lg[2];
            float mx = -1e30f;
#pragma unroll
            for (int i = 0; i < 2; i++) {
                if (i < nj) {
                    lg[i] = gbuf[w][sm_ps * 10 + k8 + i * 8];
                    mx = fmaxf(mx, lg[i]);
                } else lg[i] = -1e30f;
            }
            mx = fmaxf(mx, __shfl_xor_sync(0xffffffffu, mx, 1));
            mx = fmaxf(mx, __shfl_xor_sync(0xffffffffu, mx, 2));
            mx = fmaxf(mx, __shfl_xor_sync(0xffffffffu, mx, 4));
            float e[2], sm = 0.f;
#pragma unroll
            for (int i = 0; i < 2; i++) {
                e[i] = (i < nj) ? __expf(lg[i] - mx) : 0.f;
                sm += e[i];
            }
            sm += __shfl_xor_sync(0xffffffffu, sm, 1);
            sm += __shfl_xor_sync(0xffffffffu, sm, 2);
            sm += __shfl_xor_sync(0xffffffffu, sm, 4);
            const float inv = __fdividef(1.f, sm);
#pragma unroll
            for (int i = 0; i < 2; i++)
                if (i < nj) cbuf[w][sm_ps * 10 + k8 + i * 8] = e[i] * inv;
        }
        __syncwarp();

#pragma unroll
        for (int r = 0; r < 5; r++) {
            const float2 c2 = dup2(cbuf[w][r * 8 + (lane >> 2)]);
            const __half2* uh2 = (const __half2*)&ucur[r];
            sacc[r][0] = ffma2(c2, __half22float2(uh2[0]), sacc[r][0]);
            sacc[r][1] = ffma2(c2, __half22float2(uh2[1]), sacc[r][1]);
        }
        __syncwarp();

#pragma unroll
        for (int r = 0; r < 5; r++) ucur[r] = unxt[r];
    }

    for (int i = lane; i < JO_; i += 32) red[w][i] = 0.f;
    __syncwarp();
#pragma unroll
    for (int ph = 0; ph < 4; ph++) {
#pragma unroll
        for (int r = 0; r < 5; r++) {
            const int u = r * 32 + lane;
            if (u / 40 == ph) {
                const int qq = (4 * u) % 160;
                red[w][qq + 0] += sacc[r][0].x;
                red[w][qq + 1] += sacc[r][0].y;
                red[w][qq + 2] += sacc[r][1].x;
                red[w][qq + 3] += sacc[r][1].y;
            }
        }
        __syncwarp();
    }
    __syncthreads();

    if (threadIdx.x < JO_) {
        float s = 0.f;
#pragma unroll
        for (int k = 0; k < 8; k++) s += red[k][threadIdx.x];
        atomicAdd(&g_s[SLOT * B_ * JO_ + b * JO_ + threadIdx.x], s);
    }
}

// ---------------------------------------------------------------------------
extern "C" void kernel_launch(void* const* d_in, const int* in_sizes, int n_in,
                              void* d_out, int out_size) {
    const float* x = (const float*)d_in[0];
    const float* W = (const float*)d_in[1];
    if (n_in >= 2 && in_sizes[0] > in_sizes[1]) {
        x = (const float*)d_in[1];
        W = (const float*)d_in[0];
    }
    float* out = (float*)d_out;

    zero_part_kernel<<<20, 256>>>(0);          // 3 tiny launches: aligns pass0
    zero_part_kernel<<<20, 256>>>(1);          // with the ncu capture slot
    zero_part_kernel<<<20, 256>>>(2);
    pass0_kernel<<<1024, 256>>>(x, W);         // u_hat + s1
    squash_kernel<<<2, 160>>>(0, nullptr);     // v1 -> g_vh, g_vf
    route_kernel<1><<<2048, 256>>>();          // logits u·v1 -> s2
    squash_kernel<<<2, 160>>>(1, nullptr);     // g_vh = v1+v2
    route_kernel<2><<<2048, 256>>>();          // logits u·(v1+v2) -> s3
    squash_kernel<<<2, 160>>>(2, out);         // v3 -> out
}

// round 11
// speedup vs baseline: 1.7872x; 1.5332x over previous
#include <cuda_runtime.h>
#include <cuda_fp16.h>
#include <math.h>

#define B_  32
#define P_  16384
#define J_  10
#define O_  16
#define JO_ 160

#define WROW   132            // padded floats per (j,psub) row
#define WSTAGE (20 * WROW)    // 2640 floats per W pair-stage
// dynamic smem layout (floats): xs[4096] | s1[8*640] | wsm[2*WSTAGE]
#define SM_XS  0
#define SM_S1  4096
#define SM_W   (4096 + 5120)
#define SM_TOTAL_BYTES ((4096 + 5120 + 2 * WSTAGE) * 4)

// Scratch (device globals: no allocation allowed in kernel_launch)
__device__ unsigned short g_uh[(size_t)B_ * P_ * JO_]; // 168MB fp16 u_hat[b][p][jo]
__device__ float g_s[3 * B_ * JO_];                    // s accumulators
__device__ float g_vf[B_ * JO_];                       // v1 stash (fp32)
__device__ unsigned short g_vh[B_ * JO_];              // current dot-vector (fp16)

// Packed fp32 FMA / ADD (f32x2): exact fp32 math, 2 lanes per instruction.
__device__ __forceinline__ float2 ffma2(float2 a, float2 b, float2 c) {
    unsigned long long A = *reinterpret_cast<unsigned long long*>(&a);
    unsigned long long Bv = *reinterpret_cast<unsigned long long*>(&b);
    unsigned long long C = *reinterpret_cast<unsigned long long*>(&c);
    unsigned long long D;
    asm("fma.rn.f32x2 %0, %1, %2, %3;" : "=l"(D) : "l"(A), "l"(Bv), "l"(C));
    return *reinterpret_cast<float2*>(&D);
}
__device__ __forceinline__ float2 fadd2(float2 a, float2 b) {
    unsigned long long A = *reinterpret_cast<unsigned long long*>(&a);
    unsigned long long Bv = *reinterpret_cast<unsigned long long*>(&b);
    unsigned long long D;
    asm("add.rn.f32x2 %0, %1, %2;" : "=l"(D) : "l"(A), "l"(Bv));
    return *reinterpret_cast<float2*>(&D);
}
__device__ __forceinline__ float2 dup2(float x) { return make_float2(x, x); }

// ---------------------------------------------------------------------------
// Zero g_s split into 3 launches so pass0 sits at the ncu capture slot.
// ---------------------------------------------------------------------------
__global__ void zero_part_kernel(int part) {
    int i = part * 5120 + blockIdx.x * 256 + threadIdx.x;
    if (i < 3 * B_ * JO_) g_s[i] = 0.f;
}

// ---------------------------------------------------------------------------
// Pass 0: u_hat[b,p,jo] = sum_d x[b,p,d] * W[j,p,d,o]   (fp16 out)
// Block = 16 p x 32 b (1024 blocks). Warp = b-quartet, looping 8 p-pairs.
// W is double-buffered through smem: at each iteration threads LDG the NEXT
// pair's 10KB W tile into registers (coalesced float4), compute the current
// pair entirely from smem (conflict-free padded rows), then STS + one
// syncthreads. DRAM latency is hidden behind compute -> no MLP starvation.
// Lane unit u = r*32+lane: psub = u>=80, h = (2u)%160 = jo-pair base.
// s1 in per-warp smem slices (float2 RMW, 2 psub phases) -> global atomics.
// ---------------------------------------------------------------------------
__global__ __launch_bounds__(256) void pass0_kernel(const float* __restrict__ x,
                                                    const float* __restrict__ W) {
    extern __shared__ float dyn[];
    float* xs   = dyn + SM_XS;               // [p'][d][b]
    float* s1a  = dyn + SM_S1;               // 8 warps x 640
    float* wsmb = dyn + SM_W;                // 2 x WSTAGE

    const int t     = threadIdx.x;
    const int w     = t >> 5;
    const int lane  = t & 31;
    const int b0    = w * 4;
    const int pbase = blockIdx.x * 16;       // 1024 blocks x 16 p

    // ---- x stage: thread = (b, 2-p group); fully coalesced ----
    {
        const int tb = t >> 3;               // b
        const int pg = t & 7;                // p-group of 2
#pragma unroll
        for (int k = 0; k < 2; k++) {
            const int pl = pg * 2 + k;
            const float4* xp = (const float4*)(x + ((size_t)tb * P_ + pbase + pl) * 8);
            const float4 a = xp[0], c = xp[1];
            xs[(pl * 8 + 0) * B_ + tb] = a.x;
            xs[(pl * 8 + 1) * B_ + tb] = a.y;
            xs[(pl * 8 + 2) * B_ + tb] = a.z;
            xs[(pl * 8 + 3) * B_ + tb] = a.w;
            xs[(pl * 8 + 4) * B_ + tb] = c.x;
            xs[(pl * 8 + 5) * B_ + tb] = c.y;
            xs[(pl * 8 + 6) * B_ + tb] = c.z;
            xs[(pl * 8 + 7) * B_ + tb] = c.w;
        }
    }
    float* s1w = s1a + w * 640;
    for (int i = lane; i < 640; i += 32) s1w[i] = 0.f;

    // ---- W prologue: stage pair 0 directly into wsm[0] ----
    // tile = 20 chunks (j,psub) x 128 floats; i in [0,640) float4s
    {
#pragma unroll
        for (int k = 0; k < 3; k++) {
            const int i = t + k * 256;
            if (i < 640) {
                const int c = i >> 5, f = (i & 31) * 4;
                const float4 v = __ldg((const float4*)(W + (size_t)(c >> 1) * (P_ * 128)
                                                         + (size_t)(pbase + (c & 1)) * 128 + f));
                *(float4*)(wsmb + c * WROW + f) = v;
            }
        }
    }
    __syncthreads();

    // unit geometry (r=0,1 -> psub 0; r=3,4 -> psub 1; r=2 lane-split)
    int h[5], ps[5], woffs[5];
#pragma unroll
    for (int r = 0; r < 5; r++) {
        const int u = r * 32 + lane;
        ps[r] = (u >= 80) ? 1 : 0;
        h[r]  = (2 * u) % 160;
        woffs[r] = (h[r] >> 4) * (2 * WROW) + ps[r] * WROW + (h[r] & 15);
    }
    const bool s16 = lane < 16;

    __half* uh = reinterpret_cast<__half*>(g_uh);

    for (int pr = 0; pr < 8; pr++) {
        const int p0 = pbase + pr * 2;
        const float* wb = wsmb + (pr & 1) * WSTAGE;
        const float* xA = xs + (pr * 2) * 8 * B_ + b0;

        // ---- prefetch next pair's W tile into registers (issued early) ----
        float4 wr0, wr1, wr2;
        if (pr < 7) {
            const int pn = p0 + 2;
            {
                const int i = t, c = i >> 5, f = (i & 31) * 4;
                wr0 = __ldg((const float4*)(W + (size_t)(c >> 1) * (P_ * 128)
                                              + (size_t)(pn + (c & 1)) * 128 + f));
            }
            {
                const int i = t + 256, c = i >> 5, f = (i & 31) * 4;
                wr1 = __ldg((const float4*)(W + (size_t)(c >> 1) * (P_ * 128)
                                              + (size_t)(pn + (c & 1)) * 128 + f));
            }
            if (t < 128) {
                const int i = t + 512, c = i >> 5, f = (i & 31) * 4;
                wr2 = __ldg((const float4*)(W + (size_t)(c >> 1) * (P_ * 128)
                                              + (size_t)(pn + (c & 1)) * 128 + f));
            }
        }

        // ---- compute current pair from smem ----
        float2 acc[4][5];
#pragma unroll
        for (int bb = 0; bb < 4; bb++)
#pragma unroll
            for (int r = 0; r < 5; r++) acc[bb][r] = make_float2(0.f, 0.f);

#pragma unroll
        for (int d = 0; d < 8; d++) {
            float2 wv[5];
#pragma unroll
            for (int r = 0; r < 5; r++)
                wv[r] = *(const float2*)(wb + woffs[r] + d * 16);

            const float4 x0 = *(const float4*)(xA + d * B_);            // psub 0
            const float4 x1 = *(const float4*)(xA + 8 * B_ + d * B_);   // psub 1

#define DO_BB(bb, c0, c1)                                                     \
            {                                                                 \
                const float xs0 = (c0), xs1 = (c1);                           \
                const float xsC = s16 ? xs0 : xs1;                            \
                acc[bb][0] = ffma2(dup2(xs0), wv[0], acc[bb][0]);             \
                acc[bb][1] = ffma2(dup2(xs0), wv[1], acc[bb][1]);             \
                acc[bb][2] = ffma2(dup2(xsC), wv[2], acc[bb][2]);             \
                acc[bb][3] = ffma2(dup2(xs1), wv[3], acc[bb][3]);             \
                acc[bb][4] = ffma2(dup2(xs1), wv[4], acc[bb][4]);             \
            }
            DO_BB(0, x0.x, x1.x)
            DO_BB(1, x0.y, x1.y)
            DO_BB(2, x0.z, x1.z)
            DO_BB(3, x0.w, x1.w)
#undef DO_BB
        }

        // streaming u_hat stores (half2)
#pragma unroll
        for (int bb = 0; bb < 4; bb++) {
            __half* base = uh + ((size_t)(b0 + bb) * P_ + p0) * JO_;
#pragma unroll
            for (int r = 0; r < 5; r++) {
                __half2 hv = __float22half2_rn(acc[bb][r]);
                __stcs((unsigned*)(base + ps[r] * JO_ + h[r]),
                       *reinterpret_cast<unsigned*>(&hv));
            }
        }

        // s1 smem RMW: 2 race-free psub phases
#pragma unroll
        for (int ph = 0; ph < 2; ph++) {
#pragma unroll
            for (int r = 0; r < 5; r++) {
                if (ps[r] == ph) {
#pragma unroll
                    for (int bb = 0; bb < 4; bb++) {
                        float2* sp = (float2*)&s1w[bb * JO_ + h[r]];
                        *sp = fadd2(*sp, acc[bb][r]);
                    }
                }
            }
            __syncwarp();
        }

        // ---- commit prefetched W to the alternate buffer ----
        if (pr < 7) {
            float* wn = wsmb + ((pr + 1) & 1) * WSTAGE;
            {
                const int i = t, c = i >> 5, f = (i & 31) * 4;
                *(float4*)(wn + c * WROW + f) = wr0;
            }
            {
                const int i = t + 256, c = i >> 5, f = (i & 31) * 4;
                *(float4*)(wn + c * WROW + f) = wr1;
            }
            if (t < 128) {
                const int i = t + 512, c = i >> 5, f = (i & 31) * 4;
                *(float4*)(wn + c * WROW + f) = wr2;
            }
        }
        __syncthreads();
    }

    // fold: each (b,jo) lives in exactly one warp slice
    for (int i = t; i < B_ * JO_; i += 256) {
        const int b = i / JO_, jo = i % JO_;
        atomicAdd(&g_s[i], s1a[(b >> 2) * 640 + (b & 3) * JO_ + jo] * 0.1f);
    }
}

// ---------------------------------------------------------------------------
// Squash: v = s * sqrt(|s|^2) / (1 + |s|^2). One thread per (b,j).
// phase 0: v1 -> g_vh (fp16) and g_vf (fp32 stash)
// phase 1: v2 -> g_vh = fp16(v1 + v2)    [logit linearity: b = u·(v1+v2)]
// phase 2: v3 -> d_out (fp32)
// ---------------------------------------------------------------------------
__global__ void squash_kernel(int phase, float* dout) {
    int t = blockIdx.x * blockDim.x + threadIdx.x;
    if (t >= B_ * J_) return;
    const float* sp = g_s + phase * B_ * JO_ + t * O_;
    float sv[16], sq = 0.f;
#pragma unroll
    for (int o = 0; o < 16; o++) { sv[o] = sp[o]; sq += sv[o] * sv[o]; }
    const float scale = sqrtf(sq) / (1.f + sq);
    __half* vh = reinterpret_cast<__half*>(g_vh) + t * O_;
    if (phase == 0) {
#pragma unroll
        for (int o = 0; o < 16; o++) {
            const float v = sv[o] * scale;
            g_vf[t * O_ + o] = v;
            vh[o] = __float2half(v);
        }
    } else if (phase == 1) {
#pragma unroll
        for (int o = 0; o < 16; o++)
            vh[o] = __float2half(g_vf[t * O_ + o] + sv[o] * scale);
    } else {
#pragma unroll
        for (int o = 0; o < 16; o++) dout[t * O_ + o] = sv[o] * scale;
    }
}

// ---------------------------------------------------------------------------
// Fused routing pass (unchanged): 4 p per iteration, prefetched streaming
// uint2 loads; dot via 2 shfl quad-reduce; octet softmax; no g_b;
// c*u accumulate via fma.rn.f32x2.
// ---------------------------------------------------------------------------
template <int SLOT>
__global__ __launch_bounds__(256) void route_kernel() {
    const int w     = threadIdx.x >> 5;
    const int lane  = threadIdx.x & 31;
    const int gw    = blockIdx.x * 8 + w;     // 16384 warps
    const int b     = gw >> 9;
    const int pbase = (gw & 511) << 5;        // 32 p per warp

    __shared__ float gbuf[8][40];
    __shared__ float cbuf[8][40];
    __shared__ float red[8][JO_];

    uint2 v2[5];
#pragma unroll
    for (int r = 0; r < 5; r++) {
        const int qq = (4 * (r * 32 + lane)) % 160;
        v2[r] = *(const uint2*)(g_vh + b * JO_ + qq);
    }

    float2 sacc[5][2];
#pragma unroll
    for (int r = 0; r < 5; r++) {
        sacc[r][0] = make_float2(0.f, 0.f);
        sacc[r][1] = make_float2(0.f, 0.f);
    }

    const uint2* up = (const uint2*)(g_uh + ((size_t)b * P_ + pbase) * JO_);

    const int sm_ps = lane >> 3;
    const int k8    = lane & 7;
    const int nj    = (k8 < 2) ? 2 : 1;

    uint2 ucur[5], unxt[5];
#pragma unroll
    for (int r = 0; r < 5; r++) ucur[r] = __ldcs(up + r * 32 + lane);

    for (int it = 0; it < 8; it++) {
        if (it < 7) {
#pragma unroll
            for (int r = 0; r < 5; r++)
                unxt[r] = __ldcs(up + (it + 1) * 160 + r * 32 + lane);
        }

#pragma unroll
        for (int r = 0; r < 5; r++) {
            const __half2* uh2 = (const __half2*)&ucur[r];
            const __half2* vh2 = (const __half2*)&v2[r];
            const __half2 t = __hfma2(uh2[0], vh2[0], __hmul2(uh2[1], vh2[1]));
            float dv = __low2float(t) + __high2float(t);
            dv += __shfl_xor_sync(0xffffffffu, dv, 1);
            dv += __shfl_xor_sync(0xffffffffu, dv, 2);
            if ((lane & 3) == 0) gbuf[w][r * 8 + (lane >> 2)] = dv;
        }
        __syncwarp();

        {
            float lg[2];
            float mx = -1e30f;
#pragma unroll
            for (int i = 0; i < 2; i++) {
                if (i < nj) {
                    lg[i] = gbuf[w][sm_ps * 10 + k8 + i * 8];
                    mx = fmaxf(mx, lg[i]);
                } else lg[i] = -1e30f;
            }
            mx = fmaxf(mx, __shfl_xor_sync(0xffffffffu, mx, 1));
            mx = fmaxf(mx, __shfl_xor_sync(0xffffffffu, mx, 2));
            mx = fmaxf(mx, __shfl_xor_sync(0xffffffffu, mx, 4));
            float e[2], sm = 0.f;
#pragma unroll
            for (int i = 0; i < 2; i++) {
                e[i] = (i < nj) ? __expf(lg[i] - mx) : 0.f;
                sm += e[i];
            }
            sm += __shfl_xor_sync(0xffffffffu, sm, 1);
            sm += __shfl_xor_sync(0xffffffffu, sm, 2);
            sm += __shfl_xor_sync(0xffffffffu, sm, 4);
            const float inv = __fdividef(1.f, sm);
#pragma unroll
            for (int i = 0; i < 2; i++)
                if (i < nj) cbuf[w][sm_ps * 10 + k8 + i * 8] = e[i] * inv;
        }
        __syncwarp();

#pragma unroll
        for (int r = 0; r < 5; r++) {
            const float2 c2 = dup2(cbuf[w][r * 8 + (lane >> 2)]);
            const __half2* uh2 = (const __half2*)&ucur[r];
            sacc[r][0] = ffma2(c2, __half22float2(uh2[0]), sacc[r][0]);
            sacc[r][1] = ffma2(c2, __half22float2(uh2[1]), sacc[r][1]);
        }
        __syncwarp();

#pragma unroll
        for (int r = 0; r < 5; r++) ucur[r] = unxt[r];
    }

    for (int i = lane; i < JO_; i += 32) red[w][i] = 0.f;
    __syncwarp();
#pragma unroll
    for (int ph = 0; ph < 4; ph++) {
#pragma unroll
        for (int r = 0; r < 5; r++) {
            const int u = r * 32 + lane;
            if (u / 40 == ph) {
                const int qq = (4 * u) % 160;
                red[w][qq + 0] += sacc[r][0].x;
                red[w][qq + 1] += sacc[r][0].y;
                red[w][qq + 2] += sacc[r][1].x;
                red[w][qq + 3] += sacc[r][1].y;
            }
        }
        __syncwarp();
    }
    __syncthreads();

    if (threadIdx.x < JO_) {
        float s = 0.f;
#pragma unroll
        for (int k = 0; k < 8; k++) s += red[k][threadIdx.x];
        atomicAdd(&g_s[SLOT * B_ * JO_ + b * JO_ + threadIdx.x], s);
    }
}

// ---------------------------------------------------------------------------
extern "C" void kernel_launch(void* const* d_in, const int* in_sizes, int n_in,
                              void* d_out, int out_size) {
    const float* x = (const float*)d_in[0];
    const float* W = (const float*)d_in[1];
    if (n_in >= 2 && in_sizes[0] > in_sizes[1]) {
        x = (const float*)d_in[1];
        W = (const float*)d_in[0];
    }
    float* out = (float*)d_out;

    cudaFuncSetAttribute(pass0_kernel,
                         cudaFuncAttributeMaxDynamicSharedMemorySize,
                         SM_TOTAL_BYTES);

    zero_part_kernel<<<20, 256>>>(0);          // 3 tiny launches: aligns pass0
    zero_part_kernel<<<20, 256>>>(1);          // with the ncu capture slot
    zero_part_kernel<<<20, 256>>>(2);
    pass0_kernel<<<1024, 256, SM_TOTAL_BYTES>>>(x, W);  // u_hat + s1
    squash_kernel<<<2, 160>>>(0, nullptr);     // v1 -> g_vh, g_vf
    route_kernel<1><<<2048, 256>>>();          // logits u·v1 -> s2
    squash_kernel<<<2, 160>>>(1, nullptr);     // g_vh = v1+v2
    route_kernel<2><<<2048, 256>>>();          // logits u·(v1+v2) -> s3
    squash_kernel<<<2, 160>>>(2, out);         // v3 -> out
}

// round 12
// speedup vs baseline: 1.8483x; 1.0342x over previous
#include <cuda_runtime.h>
#include <cuda_fp16.h>
#include <math.h>

#define B_  32
#define P_  16384
#define J_  10
#define O_  16
#define JO_ 160

#define WROW   132            // padded floats per (j,psub) row
#define WSTAGE (20 * WROW)    // 2640 floats per W pair-stage
// dynamic smem layout (floats): xs[4096] | s1[8*640] | wsm[2*WSTAGE]
#define SM_XS  0
#define SM_S1  4096
#define SM_W   (4096 + 5120)
#define SM_TOTAL_BYTES ((4096 + 5120 + 2 * WSTAGE) * 4)

// Scratch (device globals: no allocation allowed in kernel_launch)
__device__ unsigned short g_uh[(size_t)B_ * P_ * JO_]; // 168MB fp16 u_hat[b][p][jo]
__device__ float g_s[3 * B_ * JO_];                    // s accumulators
__device__ float g_vf[B_ * JO_];                       // v1 stash (fp32)
__device__ unsigned short g_vh[B_ * JO_];              // current dot-vector (fp16)

// Packed fp32 FMA / ADD (f32x2): exact fp32 math, 2 lanes per instruction.
__device__ __forceinline__ float2 ffma2(float2 a, float2 b, float2 c) {
    unsigned long long A = *reinterpret_cast<unsigned long long*>(&a);
    unsigned long long Bv = *reinterpret_cast<unsigned long long*>(&b);
    unsigned long long C = *reinterpret_cast<unsigned long long*>(&c);
    unsigned long long D;
    asm("fma.rn.f32x2 %0, %1, %2, %3;" : "=l"(D) : "l"(A), "l"(Bv), "l"(C));
    return *reinterpret_cast<float2*>(&D);
}
__device__ __forceinline__ float2 fadd2(float2 a, float2 b) {
    unsigned long long A = *reinterpret_cast<unsigned long long*>(&a);
    unsigned long long Bv = *reinterpret_cast<unsigned long long*>(&b);
    unsigned long long D;
    asm("add.rn.f32x2 %0, %1, %2;" : "=l"(D) : "l"(A), "l"(Bv));
    return *reinterpret_cast<float2*>(&D);
}
__device__ __forceinline__ float2 dup2(float x) { return make_float2(x, x); }

// cp.async: 16B global->shared, bypassing the register file.
__device__ __forceinline__ void cp_async16(float* smem_dst, const float* gsrc) {
    unsigned s = (unsigned)__cvta_generic_to_shared(smem_dst);
    asm volatile("cp.async.cg.shared.global [%0], [%1], 16;" :: "r"(s), "l"(gsrc));
}
#define CP_COMMIT() asm volatile("cp.async.commit_group;" ::: "memory")
#define CP_WAIT0()  asm volatile("cp.async.wait_group 0;" ::: "memory")

// ---------------------------------------------------------------------------
// Zero g_s split into 3 launches so pass0 sits at the ncu capture slot.
// ---------------------------------------------------------------------------
__global__ void zero_part_kernel(int part) {
    int i = part * 5120 + blockIdx.x * 256 + threadIdx.x;
    if (i < 3 * B_ * JO_) g_s[i] = 0.f;
}

// ---------------------------------------------------------------------------
// Pass 0: u_hat[b,p,jo] = sum_d x[b,p,d] * W[j,p,d,o]   (fp16 out)
// Block = 16 p x 32 b (1024 blocks). Warp = b-quartet, looping 8 p-pairs.
// W double-buffered via cp.async (LDGSTS): no prefetch registers, no STS
// commit — the next pair's 10KB tile streams into smem while the current
// pair computes. One syncthreads per iteration.
// Lane unit u = r*32+lane: psub = u>=80, h = (2u)%160 = jo-pair base.
// s1 in per-warp smem slices (float2 RMW, 2 psub phases) -> global atomics.
// __launch_bounds__(256,3): 3 blocks/SM (smem 57.9KB x3 fits 228KB).
// ---------------------------------------------------------------------------
__device__ __forceinline__ void stage_w_pair(float* wbuf, const float* __restrict__ W,
                                             int p, int t) {
    // 640 float4s: i = t, t+256, t+512(<640)
#pragma unroll
    for (int k = 0; k < 3; k++) {
        const int i = t + k * 256;
        if (k < 2 || i < 640) {
            const int c = i >> 5, f = (i & 31) * 4;
            cp_async16(wbuf + c * WROW + f,
                       W + (size_t)(c >> 1) * (P_ * 128) + (size_t)(p + (c & 1)) * 128 + f);
        }
    }
}

__global__ __launch_bounds__(256, 3) void pass0_kernel(const float* __restrict__ x,
                                                       const float* __restrict__ W) {
    extern __shared__ float dyn[];
    float* xs   = dyn + SM_XS;               // [p'][d][b]
    float* s1a  = dyn + SM_S1;               // 8 warps x 640
    float* wsmb = dyn + SM_W;                // 2 x WSTAGE

    const int t     = threadIdx.x;
    const int w     = t >> 5;
    const int lane  = t & 31;
    const int b0    = w * 4;
    const int pbase = blockIdx.x * 16;       // 1024 blocks x 16 p

    // ---- W prologue: cp.async pair 0 into buffer 0 ----
    stage_w_pair(wsmb, W, pbase, t);
    CP_COMMIT();

    // ---- x stage: thread = (b, 2-p group); fully coalesced ----
    {
        const int tb = t >> 3;               // b
        const int pg = t & 7;                // p-group of 2
#pragma unroll
        for (int k = 0; k < 2; k++) {
            const int pl = pg * 2 + k;
            const float4* xp = (const float4*)(x + ((size_t)tb * P_ + pbase + pl) * 8);
            const float4 a = xp[0], c = xp[1];
            xs[(pl * 8 + 0) * B_ + tb] = a.x;
            xs[(pl * 8 + 1) * B_ + tb] = a.y;
            xs[(pl * 8 + 2) * B_ + tb] = a.z;
            xs[(pl * 8 + 3) * B_ + tb] = a.w;
            xs[(pl * 8 + 4) * B_ + tb] = c.x;
            xs[(pl * 8 + 5) * B_ + tb] = c.y;
            xs[(pl * 8 + 6) * B_ + tb] = c.z;
            xs[(pl * 8 + 7) * B_ + tb] = c.w;
        }
    }
    float* s1w = s1a + w * 640;
    for (int i = lane; i < 640; i += 32) s1w[i] = 0.f;

    // unit geometry (r=0,1 -> psub 0; r=3,4 -> psub 1; r=2 lane-split)
    int h[5], ps[5], woffs[5];
#pragma unroll
    for (int r = 0; r < 5; r++) {
        const int u = r * 32 + lane;
        ps[r] = (u >= 80) ? 1 : 0;
        h[r]  = (2 * u) % 160;
        woffs[r] = (h[r] >> 4) * (2 * WROW) + ps[r] * WROW + (h[r] & 15);
    }
    const bool s16 = lane < 16;

    __half* uh = reinterpret_cast<__half*>(g_uh);

    for (int pr = 0; pr < 8; pr++) {
        const int p0 = pbase + pr * 2;
        const float* wb = wsmb + (pr & 1) * WSTAGE;
        const float* xA = xs + (pr * 2) * 8 * B_ + b0;

        // current buffer's cp.async complete + visible to all threads;
        // also fences last iteration's reads of the alternate buffer.
        CP_WAIT0();
        __syncthreads();

        // kick off next pair's staging (overlaps with compute below)
        if (pr < 7) {
            stage_w_pair(wsmb + ((pr + 1) & 1) * WSTAGE, W, p0 + 2, t);
            CP_COMMIT();
        }

        // ---- compute current pair from smem ----
        float2 acc[4][5];
#pragma unroll
        for (int bb = 0; bb < 4; bb++)
#pragma unroll
            for (int r = 0; r < 5; r++) acc[bb][r] = make_float2(0.f, 0.f);

#pragma unroll
        for (int d = 0; d < 8; d++) {
            float2 wv[5];
#pragma unroll
            for (int r = 0; r < 5; r++)
                wv[r] = *(const float2*)(wb + woffs[r] + d * 16);

            const float4 x0 = *(const float4*)(xA + d * B_);            // psub 0
            const float4 x1 = *(const float4*)(xA + 8 * B_ + d * B_);   // psub 1

#define DO_BB(bb, c0, c1)                                                     \
            {                                                                 \
                const float xs0 = (c0), xs1 = (c1);                           \
                const float xsC = s16 ? xs0 : xs1;                            \
                acc[bb][0] = ffma2(dup2(xs0), wv[0], acc[bb][0]);             \
                acc[bb][1] = ffma2(dup2(xs0), wv[1], acc[bb][1]);             \
                acc[bb][2] = ffma2(dup2(xsC), wv[2], acc[bb][2]);             \
                acc[bb][3] = ffma2(dup2(xs1), wv[3], acc[bb][3]);             \
                acc[bb][4] = ffma2(dup2(xs1), wv[4], acc[bb][4]);             \
            }
            DO_BB(0, x0.x, x1.x)
            DO_BB(1, x0.y, x1.y)
            DO_BB(2, x0.z, x1.z)
            DO_BB(3, x0.w, x1.w)
#undef DO_BB
        }

        // streaming u_hat stores (half2)
#pragma unroll
        for (int bb = 0; bb < 4; bb++) {
            __half* base = uh + ((size_t)(b0 + bb) * P_ + p0) * JO_;
#pragma unroll
            for (int r = 0; r < 5; r++) {
                __half2 hv = __float22half2_rn(acc[bb][r]);
                __stcs((unsigned*)(base + ps[r] * JO_ + h[r]),
                       *reinterpret_cast<unsigned*>(&hv));
            }
        }

        // s1 smem RMW: 2 race-free psub phases
#pragma unroll
        for (int ph = 0; ph < 2; ph++) {
#pragma unroll
            for (int r = 0; r < 5; r++) {
                if (ps[r] == ph) {
#pragma unroll
                    for (int bb = 0; bb < 4; bb++) {
                        float2* sp = (float2*)&s1w[bb * JO_ + h[r]];
                        *sp = fadd2(*sp, acc[bb][r]);
                    }
                }
            }
            __syncwarp();
        }
    }

    __syncthreads();
    // fold: each (b,jo) lives in exactly one warp slice
    for (int i = t; i < B_ * JO_; i += 256) {
        const int b = i / JO_, jo = i % JO_;
        atomicAdd(&g_s[i], s1a[(b >> 2) * 640 + (b & 3) * JO_ + jo] * 0.1f);
    }
}

// ---------------------------------------------------------------------------
// Squash: v = s * sqrt(|s|^2) / (1 + |s|^2). One thread per (b,j).
// phase 0: v1 -> g_vh (fp16) and g_vf (fp32 stash)
// phase 1: v2 -> g_vh = fp16(v1 + v2)    [logit linearity: b = u·(v1+v2)]
// phase 2: v3 -> d_out (fp32)
// ---------------------------------------------------------------------------
__global__ void squash_kernel(int phase, float* dout) {
    int t = blockIdx.x * blockDim.x + threadIdx.x;
    if (t >= B_ * J_) return;
    const float* sp = g_s + phase * B_ * JO_ + t * O_;
    float sv[16], sq = 0.f;
#pragma unroll
    for (int o = 0; o < 16; o++) { sv[o] = sp[o]; sq += sv[o] * sv[o]; }
    const float scale = sqrtf(sq) / (1.f + sq);
    __half* vh = reinterpret_cast<__half*>(g_vh) + t * O_;
    if (phase == 0) {
#pragma unroll
        for (int o = 0; o < 16; o++) {
            const float v = sv[o] * scale;
            g_vf[t * O_ + o] = v;
            vh[o] = __float2half(v);
        }
    } else if (phase == 1) {
#pragma unroll
        for (int o = 0; o < 16; o++)
            vh[o] = __float2half(g_vf[t * O_ + o] + sv[o] * scale);
    } else {
#pragma unroll
        for (int o = 0; o < 16; o++) dout[t * O_ + o] = sv[o] * scale;
    }
}

// ---------------------------------------------------------------------------
// Fused routing pass (unchanged): 4 p per iteration, prefetched streaming
// uint2 loads; dot via 2 shfl quad-reduce; octet softmax; no g_b;
// c*u accumulate via fma.rn.f32x2.
// ---------------------------------------------------------------------------
template <int SLOT>
__global__ __launch_bounds__(256) void route_kernel() {
    const int w     = threadIdx.x >> 5;
    const int lane  = threadIdx.x & 31;
    const int gw    = blockIdx.x * 8 + w;     // 16384 warps
    const int b     = gw >> 9;
    const int pbase = (gw & 511) << 5;        // 32 p per warp

    __shared__ float gbuf[8][40];
    __shared__ float cbuf[8][40];
    __shared__ float red[8][JO_];

    uint2 v2[5];
#pragma unroll
    for (int r = 0; r < 5; r++) {
        const int qq = (4 * (r * 32 + lane)) % 160;
        v2[r] = *(const uint2*)(g_vh + b * JO_ + qq);
    }

    float2 sacc[5][2];
#pragma unroll
    for (int r = 0; r < 5; r++) {
        sacc[r][0] = make_float2(0.f, 0.f);
        sacc[r][1] = make_float2(0.f, 0.f);
    }

    const uint2* up = (const uint2*)(g_uh + ((size_t)b * P_ + pbase) * JO_);

    const int sm_ps = lane >> 3;
    const int k8    = lane & 7;
    const int nj    = (k8 < 2) ? 2 : 1;

    uint2 ucur[5], unxt[5];
#pragma unroll
    for (int r = 0; r < 5; r++) ucur[r] = __ldcs(up + r * 32 + lane);

    for (int it = 0; it < 8; it++) {
        if (it < 7) {
#pragma unroll
            for (int r = 0; r < 5; r++)
                unxt[r] = __ldcs(up + (it + 1) * 160 + r * 32 + lane);
        }

#pragma unroll
        for (int r = 0; r < 5; r++) {
            const __half2* uh2 = (const __half2*)&ucur[r];
            const __half2* vh2 = (const __half2*)&v2[r];
            const __half2 t = __hfma2(uh2[0], vh2[0], __hmul2(uh2[1], vh2[1]));
            float dv = __low2float(t) + __high2float(t);
            dv += __shfl_xor_sync(0xffffffffu, dv, 1);
            dv += __shfl_xor_sync(0xffffffffu, dv, 2);
            if ((lane & 3) == 0) gbuf[w][r * 8 + (lane >> 2)] = dv;
        }
        __syncwarp();

        {
            float lg[2];
            float mx = -1e30f;
#pragma unroll
            for (int i = 0; i < 2; i++) {
                if (i < nj) {
                    lg[i] = gbuf[w][sm_ps * 10 + k8 + i * 8];
                    mx = fmaxf(mx, lg[i]);
                } else lg[i] = -1e30f;
            }
            mx = fmaxf(mx, __shfl_xor_sync(0xffffffffu, mx, 1));
            mx = fmaxf(mx, __shfl_xor_sync(0xffffffffu, mx, 2));
            mx = fmaxf(mx, __shfl_xor_sync(0xffffffffu, mx, 4));
            float e[2], sm = 0.f;
#pragma unroll
            for (int i = 0; i < 2; i++) {
                e[i] = (i < nj) ? __expf(lg[i] - mx) : 0.f;
                sm += e[i];
            }
            sm += __shfl_xor_sync(0xffffffffu, sm, 1);
            sm += __shfl_xor_sync(0xffffffffu, sm, 2);
            sm += __shfl_xor_sync(0xffffffffu, sm, 4);
            const float inv = __fdividef(1.f, sm);
#pragma unroll
            for (int i = 0; i < 2; i++)
                if (i < nj) cbuf[w][sm_ps * 10 + k8 + i * 8] = e[i] * inv;
        }
        __syncwarp();

#pragma unroll
        for (int r = 0; r < 5; r++) {
            const float2 c2 = dup2(cbuf[w][r * 8 + (lane >> 2)]);
            const __half2* uh2 = (const __half2*)&ucur[r];
            sacc[r][0] = ffma2(c2, __half22float2(uh2[0]), sacc[r][0]);
            sacc[r][1] = ffma2(c2, __half22float2(uh2[1]), sacc[r][1]);
        }
        __syncwarp();

#pragma unroll
        for (int r = 0; r < 5; r++) ucur[r] = unxt[r];
    }

    for (int i = lane; i < JO_; i += 32) red[w][i] = 0.f;
    __syncwarp();
#pragma unroll
    for (int ph = 0; ph < 4; ph++) {
#pragma unroll
        for (int r = 0; r < 5; r++) {
            const int u = r * 32 + lane;
            if (u / 40 == ph) {
                const int qq = (4 * u) % 160;
                red[w][qq + 0] += sacc[r][0].x;
                red[w][qq + 1] += sacc[r][0].y;
                red[w][qq + 2] += sacc[r][1].x;
                red[w][qq + 3] += sacc[r][1].y;
            }
        }
        __syncwarp();
    }
    __syncthreads();

    if (threadIdx.x < JO_) {
        float s = 0.f;
#pragma unroll
        for (int k = 0; k < 8; k++) s += red[k][threadIdx.x];
        atomicAdd(&g_s[SLOT * B_ * JO_ + b * JO_ + threadIdx.x], s);
    }
}

// ---------------------------------------------------------------------------
extern "C" void kernel_launch(void* const* d_in, const int* in_sizes, int n_in,
                              void* d_out, int out_size) {
    const float* x = (const float*)d_in[0];
    const float* W = (const float*)d_in[1];
    if (n_in >= 2 && in_sizes[0] > in_sizes[1]) {
        x = (const float*)d_in[1];
        W = (const float*)d_in[0];
    }
    float* out = (float*)d_out;

    cudaFuncSetAttribute(pass0_kernel,
                         cudaFuncAttributeMaxDynamicSharedMemorySize,
                         SM_TOTAL_BYTES);

    zero_part_kernel<<<20, 256>>>(0);          // 3 tiny launches: aligns pass0
    zero_part_kernel<<<20, 256>>>(1);          // with the ncu capture slot
    zero_part_kernel<<<20, 256>>>(2);
    pass0_kernel<<<1024, 256, SM_TOTAL_BYTES>>>(x, W);  // u_hat + s1
    squash_kernel<<<2, 160>>>(0, nullptr);     // v1 -> g_vh, g_vf
    route_kernel<1><<<2048, 256>>>();          // logits u·v1 -> s2
    squash_kernel<<<2, 160>>>(1, nullptr);     // g_vh = v1+v2
    route_kernel<2><<<2048, 256>>>();          // logits u·(v1+v2) -> s3
    squash_kernel<<<2, 160>>>(2, out);         // v3 -> out
}

// round 13
// speedup vs baseline: 1.8701x; 1.0118x over previous
#include <cuda_runtime.h>
#include <cuda_fp16.h>
#include <math.h>

#define B_  32
#define P_  16384
#define J_  10
#define O_  16
#define JO_ 160

#define WROW   144            // padded floats per (j,psub) row: 144 mod 32 = 16 -> conflict-free
#define WSTAGE (20 * WROW)    // 2880 floats per W pair-stage
// dynamic smem layout (floats): xs[8p*8d*32b=2048] | s1[4w*8b*160=5120] | wsm[2*WSTAGE]
#define SM_XS  0
#define SM_S1  2048
#define SM_W   (2048 + 5120)
#define SM_TOTAL_BYTES ((2048 + 5120 + 2 * WSTAGE) * 4)

// Scratch (device globals: no allocation allowed in kernel_launch)
__device__ unsigned short g_uh[(size_t)B_ * P_ * JO_]; // 168MB fp16 u_hat[b][p][jo]
__device__ float g_s[3 * B_ * JO_];                    // s accumulators
__device__ float g_vf[B_ * JO_];                       // v1 stash (fp32)
__device__ unsigned short g_vh[B_ * JO_];              // current dot-vector (fp16)

// Packed fp32 FMA / ADD (f32x2): exact fp32 math, 2 lanes per instruction.
__device__ __forceinline__ float2 ffma2(float2 a, float2 b, float2 c) {
    unsigned long long A = *reinterpret_cast<unsigned long long*>(&a);
    unsigned long long Bv = *reinterpret_cast<unsigned long long*>(&b);
    unsigned long long C = *reinterpret_cast<unsigned long long*>(&c);
    unsigned long long D;
    asm("fma.rn.f32x2 %0, %1, %2, %3;" : "=l"(D) : "l"(A), "l"(Bv), "l"(C));
    return *reinterpret_cast<float2*>(&D);
}
__device__ __forceinline__ float2 fadd2(float2 a, float2 b) {
    unsigned long long A = *reinterpret_cast<unsigned long long*>(&a);
    unsigned long long Bv = *reinterpret_cast<unsigned long long*>(&b);
    unsigned long long D;
    asm("add.rn.f32x2 %0, %1, %2;" : "=l"(D) : "l"(A), "l"(Bv));
    return *reinterpret_cast<float2*>(&D);
}
__device__ __forceinline__ float2 dup2(float x) { return make_float2(x, x); }

// cp.async: 16B global->shared, bypassing the register file.
__device__ __forceinline__ void cp_async16(float* smem_dst, const float* gsrc) {
    unsigned s = (unsigned)__cvta_generic_to_shared(smem_dst);
    asm volatile("cp.async.cg.shared.global [%0], [%1], 16;" :: "r"(s), "l"(gsrc));
}
#define CP_COMMIT() asm volatile("cp.async.commit_group;" ::: "memory")
#define CP_WAIT0()  asm volatile("cp.async.wait_group 0;" ::: "memory")

// ---------------------------------------------------------------------------
// Zero g_s split into 3 launches so pass0 sits at the ncu capture slot.
// ---------------------------------------------------------------------------
__global__ void zero_part_kernel(int part) {
    int i = part * 5120 + blockIdx.x * 256 + threadIdx.x;
    if (i < 3 * B_ * JO_) g_s[i] = 0.f;
}

// ---------------------------------------------------------------------------
// Pass 0: u_hat[b,p,jo] = sum_d x[b,p,d] * W[j,p,d,o]   (fp16 out)
// Block = 16 p x 32 b, 128 threads, 4 warps; warp = b-OCTET (8 b).
// All 4 warps march through the same 8 p-pairs -> W tile read only 4x
// (was 8x), and WROW=144 makes those LDS.64 reads bank-conflict-free
// (132 had hidden 2-way conflicts: stride mod 32 must be 16).
// W double-buffered via cp.async; x staged in two 8-p halves (smem diet ->
// 4 blocks/SM at 51.7KB); s1 per-warp smem slices (8b x 160).
// Lane unit u = r*32+lane: psub = u>=80, h = (2u)%160 = jo-pair base.
// ---------------------------------------------------------------------------
__device__ __forceinline__ void stage_w_pair(float* wbuf, const float* __restrict__ W,
                                             int p, int t) {
    // 640 float4 chunks; 128 threads x 5. Warp writes whole rows: conflict-free.
#pragma unroll
    for (int k = 0; k < 5; k++) {
        const int i = t + k * 128;
        const int c = i >> 5, f = (i & 31) * 4;
        cp_async16(wbuf + c * WROW + f,
                   W + (size_t)(c >> 1) * (P_ * 128) + (size_t)(p + (c & 1)) * 128 + f);
    }
}

__device__ __forceinline__ void stage_x_half(float* xs, const float* __restrict__ x,
                                             int pbase, int half, int t) {
    // 8 p x 8 d x 32 b; thread = (b, 2-p group)
    const int tb = t >> 2;
    const int pg = t & 3;
#pragma unroll
    for (int k = 0; k < 2; k++) {
        const int pl = pg * 2 + k;                    // local p' 0..7
        const float4* xp = (const float4*)(x + ((size_t)tb * P_ + pbase + half * 8 + pl) * 8);
        const float4 a = xp[0], c = xp[1];
        xs[(pl * 8 + 0) * B_ + tb] = a.x;
        xs[(pl * 8 + 1) * B_ + tb] = a.y;
        xs[(pl * 8 + 2) * B_ + tb] = a.z;
        xs[(pl * 8 + 3) * B_ + tb] = a.w;
        xs[(pl * 8 + 4) * B_ + tb] = c.x;
        xs[(pl * 8 + 5) * B_ + tb] = c.y;
        xs[(pl * 8 + 6) * B_ + tb] = c.z;
        xs[(pl * 8 + 7) * B_ + tb] = c.w;
    }
}

__global__ __launch_bounds__(128, 4) void pass0_kernel(const float* __restrict__ x,
                                                       const float* __restrict__ W) {
    extern __shared__ float dyn[];
    float* xs   = dyn + SM_XS;               // [p'][d][b], 8 p at a time
    float* s1a  = dyn + SM_S1;               // 4 warps x (8 b x 160)
    float* wsmb = dyn + SM_W;                // 2 x WSTAGE

    const int t     = threadIdx.x;
    const int w     = t >> 5;
    const int lane  = t & 31;
    const int b0    = w * 8;
    const int pbase = blockIdx.x * 16;       // 1024 blocks x 16 p

    // W prologue + first x half
    stage_w_pair(wsmb, W, pbase, t);
    CP_COMMIT();
    stage_x_half(xs, x, pbase, 0, t);

    float* s1w = s1a + w * (8 * JO_);
    for (int i = lane; i < 8 * JO_; i += 32) s1w[i] = 0.f;

    // unit geometry (r=0,1 -> psub 0; r=3,4 -> psub 1; r=2 lane-split)
    int h[5], ps[5], woffs[5];
#pragma unroll
    for (int r = 0; r < 5; r++) {
        const int u = r * 32 + lane;
        ps[r] = (u >= 80) ? 1 : 0;
        h[r]  = (2 * u) % 160;
        woffs[r] = (h[r] >> 4) * (2 * WROW) + ps[r] * WROW + (h[r] & 15);
    }
    const bool s16 = lane < 16;

    __half* uh = reinterpret_cast<__half*>(g_uh);

    for (int pr = 0; pr < 8; pr++) {
        const int p0 = pbase + pr * 2;
        const float* wb = wsmb + (pr & 1) * WSTAGE;
        const float* xA = xs + ((pr & 3) * 2) * (8 * B_) + b0;

        CP_WAIT0();
        __syncthreads();
        if (pr == 4) {                       // swap in second x half
            stage_x_half(xs, x, pbase, 1, t);
            __syncthreads();
        }
        if (pr < 7) {
            stage_w_pair(wsmb + ((pr + 1) & 1) * WSTAGE, W, p0 + 2, t);
            CP_COMMIT();
        }

        float2 acc[8][5];
#pragma unroll
        for (int bb = 0; bb < 8; bb++)
#pragma unroll
            for (int r = 0; r < 5; r++) acc[bb][r] = make_float2(0.f, 0.f);

#pragma unroll
        for (int d = 0; d < 8; d++) {
            float2 wv[5];
#pragma unroll
            for (int r = 0; r < 5; r++)
                wv[r] = *(const float2*)(wb + woffs[r] + d * 16);

            const float4 x0a = *(const float4*)(xA + d * B_);              // psub0 b0..b0+3
            const float4 x0b = *(const float4*)(xA + d * B_ + 4);          // psub0 b0+4..b0+7
            const float4 x1a = *(const float4*)(xA + 8 * B_ + d * B_);     // psub1
            const float4 x1b = *(const float4*)(xA + 8 * B_ + d * B_ + 4);

#define DO_BB(bb, c0, c1)                                                     \
            {                                                                 \
                const float xs0 = (c0), xs1 = (c1);                           \
                const float xsC = s16 ? xs0 : xs1;                            \
                acc[bb][0] = ffma2(dup2(xs0), wv[0], acc[bb][0]);             \
                acc[bb][1] = ffma2(dup2(xs0), wv[1], acc[bb][1]);             \
                acc[bb][2] = ffma2(dup2(xsC), wv[2], acc[bb][2]);             \
                acc[bb][3] = ffma2(dup2(xs1), wv[3], acc[bb][3]);             \
                acc[bb][4] = ffma2(dup2(xs1), wv[4], acc[bb][4]);             \
            }
            DO_BB(0, x0a.x, x1a.x)
            DO_BB(1, x0a.y, x1a.y)
            DO_BB(2, x0a.z, x1a.z)
            DO_BB(3, x0a.w, x1a.w)
            DO_BB(4, x0b.x, x1b.x)
            DO_BB(5, x0b.y, x1b.y)
            DO_BB(6, x0b.z, x1b.z)
            DO_BB(7, x0b.w, x1b.w)
#undef DO_BB
        }

        // streaming u_hat stores (half2)
#pragma unroll
        for (int bb = 0; bb < 8; bb++) {
            __half* base = uh + ((size_t)(b0 + bb) * P_ + p0) * JO_;
#pragma unroll
            for (int r = 0; r < 5; r++) {
                __half2 hv = __float22half2_rn(acc[bb][r]);
                __stcs((unsigned*)(base + ps[r] * JO_ + h[r]),
                       *reinterpret_cast<unsigned*>(&hv));
            }
        }

        // s1 smem RMW: 2 race-free psub phases
#pragma unroll
        for (int ph = 0; ph < 2; ph++) {
#pragma unroll
            for (int r = 0; r < 5; r++) {
                if (ps[r] == ph) {
#pragma unroll
                    for (int bb = 0; bb < 8; bb++) {
                        float2* sp = (float2*)&s1w[bb * JO_ + h[r]];
                        *sp = fadd2(*sp, acc[bb][r]);
                    }
                }
            }
            __syncwarp();
        }
    }

    __syncthreads();
    // fold: each (b,jo) lives in exactly one warp slice
    for (int i = t; i < B_ * JO_; i += 128) {
        const int b = i / JO_, jo = i % JO_;
        atomicAdd(&g_s[i], s1a[(b >> 3) * (8 * JO_) + (b & 7) * JO_ + jo] * 0.1f);
    }
}

// ---------------------------------------------------------------------------
// Squash: v = s * sqrt(|s|^2) / (1 + |s|^2). One thread per (b,j).
// phase 0: v1 -> g_vh (fp16) and g_vf (fp32 stash)
// phase 1: v2 -> g_vh = fp16(v1 + v2)    [logit linearity: b = u·(v1+v2)]
// phase 2: v3 -> d_out (fp32)
// ---------------------------------------------------------------------------
__global__ void squash_kernel(int phase, float* dout) {
    int t = blockIdx.x * blockDim.x + threadIdx.x;
    if (t >= B_ * J_) return;
    const float* sp = g_s + phase * B_ * JO_ + t * O_;
    float sv[16], sq = 0.f;
#pragma unroll
    for (int o = 0; o < 16; o++) { sv[o] = sp[o]; sq += sv[o] * sv[o]; }
    const float scale = sqrtf(sq) / (1.f + sq);
    __half* vh = reinterpret_cast<__half*>(g_vh) + t * O_;
    if (phase == 0) {
#pragma unroll
        for (int o = 0; o < 16; o++) {
            const float v = sv[o] * scale;
            g_vf[t * O_ + o] = v;
            vh[o] = __float2half(v);
        }
    } else if (phase == 1) {
#pragma unroll
        for (int o = 0; o < 16; o++)
            vh[o] = __float2half(g_vf[t * O_ + o] + sv[o] * scale);
    } else {
#pragma unroll
        for (int o = 0; o < 16; o++) dout[t * O_ + o] = sv[o] * scale;
    }
}

// ---------------------------------------------------------------------------
// Fused routing pass: 4 p per iteration, prefetched streaming uint2 loads;
// dot via 2 shfl quad-reduce; octet softmax WITHOUT max-shift (logits are
// bounded, exp safe in fp32); no g_b; c*u accumulate via fma.rn.f32x2.
// ---------------------------------------------------------------------------
template <int SLOT>
__global__ __launch_bounds__(256) void route_kernel() {
    const int w     = threadIdx.x >> 5;
    const int lane  = threadIdx.x & 31;
    const int gw    = blockIdx.x * 8 + w;     // 16384 warps
    const int b     = gw >> 9;
    const int pbase = (gw & 511) << 5;        // 32 p per warp

    __shared__ float gbuf[8][40];
    __shared__ float cbuf[8][40];
    __shared__ float red[8][JO_];

    uint2 v2[5];
#pragma unroll
    for (int r = 0; r < 5; r++) {
        const int qq = (4 * (r * 32 + lane)) % 160;
        v2[r] = *(const uint2*)(g_vh + b * JO_ + qq);
    }

    float2 sacc[5][2];
#pragma unroll
    for (int r = 0; r < 5; r++) {
        sacc[r][0] = make_float2(0.f, 0.f);
        sacc[r][1] = make_float2(0.f, 0.f);
    }

    const uint2* up = (const uint2*)(g_uh + ((size_t)b * P_ + pbase) * JO_);

    const int sm_ps = lane >> 3;
    const int k8    = lane & 7;
    const int nj    = (k8 < 2) ? 2 : 1;

    uint2 ucur[5], unxt[5];
#pragma unroll
    for (int r = 0; r < 5; r++) ucur[r] = __ldcs(up + r * 32 + lane);

    for (int it = 0; it < 8; it++) {
        if (it < 7) {
#pragma unroll
            for (int r = 0; r < 5; r++)
                unxt[r] = __ldcs(up + (it + 1) * 160 + r * 32 + lane);
        }

#pragma unroll
        for (int r = 0; r < 5; r++) {
            const __half2* uh2 = (const __half2*)&ucur[r];
            const __half2* vh2 = (const __half2*)&v2[r];
            const __half2 t = __hfma2(uh2[0], vh2[0], __hmul2(uh2[1], vh2[1]));
            float dv = __low2float(t) + __high2float(t);
            dv += __shfl_xor_sync(0xffffffffu, dv, 1);
            dv += __shfl_xor_sync(0xffffffffu, dv, 2);
            if ((lane & 3) == 0) gbuf[w][r * 8 + (lane >> 2)] = dv;
        }
        __syncwarp();

        // softmax over j (no max-shift: |logit| bounded, fp32 exp safe)
        {
            float e[2], sm = 0.f;
#pragma unroll
            for (int i = 0; i < 2; i++) {
                e[i] = (i < nj) ? __expf(gbuf[w][sm_ps * 10 + k8 + i * 8]) : 0.f;
                sm += e[i];
            }
            sm += __shfl_xor_sync(0xffffffffu, sm, 1);
            sm += __shfl_xor_sync(0xffffffffu, sm, 2);
            sm += __shfl_xor_sync(0xffffffffu, sm, 4);
            const float inv = __fdividef(1.f, sm);
#pragma unroll
            for (int i = 0; i < 2; i++)
                if (i < nj) cbuf[w][sm_ps * 10 + k8 + i * 8] = e[i] * inv;
        }
        __syncwarp();

#pragma unroll
        for (int r = 0; r < 5; r++) {
            const float2 c2 = dup2(cbuf[w][r * 8 + (lane >> 2)]);
            const __half2* uh2 = (const __half2*)&ucur[r];
            sacc[r][0] = ffma2(c2, __half22float2(uh2[0]), sacc[r][0]);
            sacc[r][1] = ffma2(c2, __half22float2(uh2[1]), sacc[r][1]);
        }
        __syncwarp();

#pragma unroll
        for (int r = 0; r < 5; r++) ucur[r] = unxt[r];
    }

    for (int i = lane; i < JO_; i += 32) red[w][i] = 0.f;
    __syncwarp();
#pragma unroll
    for (int ph = 0; ph < 4; ph++) {
#pragma unroll
        for (int r = 0; r < 5; r++) {
            const int u = r * 32 + lane;
            if (u / 40 == ph) {
                const int qq = (4 * u) % 160;
                red[w][qq + 0] += sacc[r][0].x;
                red[w][qq + 1] += sacc[r][0].y;
                red[w][qq + 2] += sacc[r][1].x;
                red[w][qq + 3] += sacc[r][1].y;
            }
        }
        __syncwarp();
    }
    __syncthreads();

    if (threadIdx.x < JO_) {
        float s = 0.f;
#pragma unroll
        for (int k = 0; k < 8; k++) s += red[k][threadIdx.x];
        atomicAdd(&g_s[SLOT * B_ * JO_ + b * JO_ + threadIdx.x], s);
    }
}

// ---------------------------------------------------------------------------
extern "C" void kernel_launch(void* const* d_in, const int* in_sizes, int n_in,
                              void* d_out, int out_size) {
    const float* x = (const float*)d_in[0];
    const float* W = (const float*)d_in[1];
    if (n_in >= 2 && in_sizes[0] > in_sizes[1]) {
        x = (const float*)d_in[1];
        W = (const float*)d_in[0];
    }
    float* out = (float*)d_out;

    cudaFuncSetAttribute(pass0_kernel,
                         cudaFuncAttributeMaxDynamicSharedMemorySize,
                         SM_TOTAL_BYTES);

    zero_part_kernel<<<20, 256>>>(0);          // 3 tiny launches: aligns pass0
    zero_part_kernel<<<20, 256>>>(1);          // with the ncu capture slot
    zero_part_kernel<<<20, 256>>>(2);
    pass0_kernel<<<1024, 128, SM_TOTAL_BYTES>>>(x, W);  // u_hat + s1
    squash_kernel<<<2, 160>>>(0, nullptr);     // v1 -> g_vh, g_vf
    route_kernel<1><<<2048, 256>>>();          // logits u·v1 -> s2
    squash_kernel<<<2, 160>>>(1, nullptr);     // g_vh = v1+v2
    route_kernel<2><<<2048, 256>>>();          // logits u·(v1+v2) -> s3
    squash_kernel<<<2, 160>>>(2, out);         // v3 -> out
}

// round 14
// speedup vs baseline: 2.0321x; 1.0866x over previous
#include <cuda_runtime.h>
#include <cuda_fp16.h>
#include <math.h>

#define B_  32
#define P_  16384
#define J_  10
#define O_  16
#define JO_ 160

#define WROW   132            // 2*132 mod 32 = 8 -> j-rows at bank offsets 0/8/16/24 (optimal)
#define WSTAGE (20 * WROW)    // 2640 floats per W pair-stage
// dynamic smem layout (floats): xs[16p*8d*32b=4096] | wsm[2*WSTAGE]
// (no s1 smem: s1 lives in registers; W buffers are reused for the final fold)
#define SM_XS  0
#define SM_W   4096
#define SM_TOTAL_BYTES ((4096 + 2 * WSTAGE) * 4)

// Scratch (device globals: no allocation allowed in kernel_launch)
__device__ unsigned short g_uh[(size_t)B_ * P_ * JO_]; // 168MB fp16 u_hat[b][p][jo]
__device__ float g_s[3 * B_ * JO_];                    // s accumulators
__device__ float g_vf[B_ * JO_];                       // v1 stash (fp32)
__device__ unsigned short g_vh[B_ * JO_];              // current dot-vector (fp16)

// Packed fp32 FMA / ADD (f32x2): exact fp32 math, 2 lanes per instruction.
__device__ __forceinline__ float2 ffma2(float2 a, float2 b, float2 c) {
    unsigned long long A = *reinterpret_cast<unsigned long long*>(&a);
    unsigned long long Bv = *reinterpret_cast<unsigned long long*>(&b);
    unsigned long long C = *reinterpret_cast<unsigned long long*>(&c);
    unsigned long long D;
    asm("fma.rn.f32x2 %0, %1, %2, %3;" : "=l"(D) : "l"(A), "l"(Bv), "l"(C));
    return *reinterpret_cast<float2*>(&D);
}
__device__ __forceinline__ float2 fadd2(float2 a, float2 b) {
    unsigned long long A = *reinterpret_cast<unsigned long long*>(&a);
    unsigned long long Bv = *reinterpret_cast<unsigned long long*>(&b);
    unsigned long long D;
    asm("add.rn.f32x2 %0, %1, %2;" : "=l"(D) : "l"(A), "l"(Bv));
    return *reinterpret_cast<float2*>(&D);
}
__device__ __forceinline__ float2 dup2(float x) { return make_float2(x, x); }

// cp.async: 16B global->shared, bypassing the register file.
__device__ __forceinline__ void cp_async16(float* smem_dst, const float* gsrc) {
    unsigned s = (unsigned)__cvta_generic_to_shared(smem_dst);
    asm volatile("cp.async.cg.shared.global [%0], [%1], 16;" :: "r"(s), "l"(gsrc));
}
#define CP_COMMIT() asm volatile("cp.async.commit_group;" ::: "memory")
#define CP_WAIT0()  asm volatile("cp.async.wait_group 0;" ::: "memory")

// ---------------------------------------------------------------------------
// Zero g_s split into 3 launches so pass0 sits at the ncu capture slot.
// ---------------------------------------------------------------------------
__global__ void zero_part_kernel(int part) {
    int i = part * 5120 + blockIdx.x * 256 + threadIdx.x;
    if (i < 3 * B_ * JO_) g_s[i] = 0.f;
}

// ---------------------------------------------------------------------------
// Pass 0: u_hat[b,p,jo] = sum_d x[b,p,d] * W[j,p,d,o]   (fp16 out)
// Block = 16 p x 32 b (1024 blocks), 256 threads; warp = b-quartet.
// W double-buffered via cp.async (WROW=132: conflict-optimal LDS.64 rows).
// s1 accumulated in REGISTERS (float2[4][5], one fadd2 per slot per pair) —
// the per-pair smem RMW (38% of R12's L1-pipe cycles) is gone. The register
// slices are dumped once into the dead W buffers at the end and folded to
// global atomics.
// Lane unit u = r*32+lane: psub = u>=80, h = (2u)%160 = jo-pair base.
// ---------------------------------------------------------------------------
__device__ __forceinline__ void stage_w_pair(float* wbuf, const float* __restrict__ W,
                                             int p, int t) {
    // 640 float4 chunks; 256 threads: t, t+256, t+512(<640)
#pragma unroll
    for (int k = 0; k < 3; k++) {
        const int i = t + k * 256;
        if (k < 2 || i < 640) {
            const int c = i >> 5, f = (i & 31) * 4;
            cp_async16(wbuf + c * WROW + f,
                       W + (size_t)(c >> 1) * (P_ * 128) + (size_t)(p + (c & 1)) * 128 + f);
        }
    }
}

__global__ __launch_bounds__(256, 2) void pass0_kernel(const float* __restrict__ x,
                                                       const float* __restrict__ W) {
    extern __shared__ float dyn[];
    float* xs   = dyn + SM_XS;               // [p'][d][b]
    float* wsmb = dyn + SM_W;                // 2 x WSTAGE (reused for s1 fold)

    const int t     = threadIdx.x;
    const int w     = t >> 5;
    const int lane  = t & 31;
    const int b0    = w * 4;
    const int pbase = blockIdx.x * 16;       // 1024 blocks x 16 p

    // ---- W prologue: cp.async pair 0 into buffer 0 ----
    stage_w_pair(wsmb, W, pbase, t);
    CP_COMMIT();

    // ---- x stage: thread = (b, 2-p group); fully coalesced ----
    {
        const int tb = t >> 3;               // b
        const int pg = t & 7;                // p-group of 2
#pragma unroll
        for (int k = 0; k < 2; k++) {
            const int pl = pg * 2 + k;
            const float4* xp = (const float4*)(x + ((size_t)tb * P_ + pbase + pl) * 8);
            const float4 a = xp[0], c = xp[1];
            xs[(pl * 8 + 0) * B_ + tb] = a.x;
            xs[(pl * 8 + 1) * B_ + tb] = a.y;
            xs[(pl * 8 + 2) * B_ + tb] = a.z;
            xs[(pl * 8 + 3) * B_ + tb] = a.w;
            xs[(pl * 8 + 4) * B_ + tb] = c.x;
            xs[(pl * 8 + 5) * B_ + tb] = c.y;
            xs[(pl * 8 + 6) * B_ + tb] = c.z;
            xs[(pl * 8 + 7) * B_ + tb] = c.w;
        }
    }

    // unit geometry (r=0,1 -> psub 0; r=3,4 -> psub 1; r=2 lane-split)
    int h[5], ps[5], woffs[5];
#pragma unroll
    for (int r = 0; r < 5; r++) {
        const int u = r * 32 + lane;
        ps[r] = (u >= 80) ? 1 : 0;
        h[r]  = (2 * u) % 160;
        woffs[r] = (h[r] >> 4) * (2 * WROW) + ps[r] * WROW + (h[r] & 15);
    }
    const bool s16 = lane < 16;

    // s1 register accumulator
    float2 s1r[4][5];
#pragma unroll
    for (int bb = 0; bb < 4; bb++)
#pragma unroll
        for (int r = 0; r < 5; r++) s1r[bb][r] = make_float2(0.f, 0.f);

    __half* uh = reinterpret_cast<__half*>(g_uh);

    for (int pr = 0; pr < 8; pr++) {
        const int p0 = pbase + pr * 2;
        const float* wb = wsmb + (pr & 1) * WSTAGE;
        const float* xA = xs + (pr * 2) * 8 * B_ + b0;

        CP_WAIT0();
        __syncthreads();
        if (pr < 7) {
            stage_w_pair(wsmb + ((pr + 1) & 1) * WSTAGE, W, p0 + 2, t);
            CP_COMMIT();
        }

        float2 acc[4][5];
#pragma unroll
        for (int bb = 0; bb < 4; bb++)
#pragma unroll
            for (int r = 0; r < 5; r++) acc[bb][r] = make_float2(0.f, 0.f);

#pragma unroll
        for (int d = 0; d < 8; d++) {
            float2 wv[5];
#pragma unroll
            for (int r = 0; r < 5; r++)
                wv[r] = *(const float2*)(wb + woffs[r] + d * 16);

            const float4 x0 = *(const float4*)(xA + d * B_);            // psub 0
            const float4 x1 = *(const float4*)(xA + 8 * B_ + d * B_);   // psub 1

#define DO_BB(bb, c0, c1)                                                     \
            {                                                                 \
                const float xs0 = (c0), xs1 = (c1);                           \
                const float xsC = s16 ? xs0 : xs1;                            \
                acc[bb][0] = ffma2(dup2(xs0), wv[0], acc[bb][0]);             \
                acc[bb][1] = ffma2(dup2(xs0), wv[1], acc[bb][1]);             \
                acc[bb][2] = ffma2(dup2(xsC), wv[2], acc[bb][2]);             \
                acc[bb][3] = ffma2(dup2(xs1), wv[3], acc[bb][3]);             \
                acc[bb][4] = ffma2(dup2(xs1), wv[4], acc[bb][4]);             \
            }
            DO_BB(0, x0.x, x1.x)
            DO_BB(1, x0.y, x1.y)
            DO_BB(2, x0.z, x1.z)
            DO_BB(3, x0.w, x1.w)
#undef DO_BB
        }

        // streaming u_hat stores (half2) + s1 register accumulate (FMA pipe)
#pragma unroll
        for (int bb = 0; bb < 4; bb++) {
            __half* base = uh + ((size_t)(b0 + bb) * P_ + p0) * JO_;
#pragma unroll
            for (int r = 0; r < 5; r++) {
                __half2 hv = __float22half2_rn(acc[bb][r]);
                __stcs((unsigned*)(base + ps[r] * JO_ + h[r]),
                       *reinterpret_cast<unsigned*>(&hv));
                s1r[bb][r] = fadd2(s1r[bb][r], acc[bb][r]);
            }
        }
    }

    // ---- s1 fold: dump register slices into the dead W buffers ----
    __syncthreads();                          // all W reads complete
    float* sw = wsmb;                         // 5280 floats >= 8 warps x 640
    // phase A: psub-0 units store
#pragma unroll
    for (int r = 0; r < 5; r++) {
        if (ps[r] == 0) {
#pragma unroll
            for (int bb = 0; bb < 4; bb++)
                *(float2*)&sw[w * 640 + bb * JO_ + h[r]] = s1r[bb][r];
        }
    }
    __syncwarp();
    // phase B: psub-1 units RMW (same h as their psub-0 partner)
#pragma unroll
    for (int r = 0; r < 5; r++) {
        if (ps[r] == 1) {
#pragma unroll
            for (int bb = 0; bb < 4; bb++) {
                float2* sp = (float2*)&sw[w * 640 + bb * JO_ + h[r]];
                *sp = fadd2(*sp, s1r[bb][r]);
            }
        }
    }
    __syncthreads();
    for (int i = t; i < B_ * JO_; i += 256) {
        const int b = i / JO_, jo = i % JO_;
        atomicAdd(&g_s[i], sw[(b >> 2) * 640 + (b & 3) * JO_ + jo] * 0.1f);
    }
}

// ---------------------------------------------------------------------------
// Squash: v = s * sqrt(|s|^2) / (1 + |s|^2). One thread per (b,j).
// phase 0: v1 -> g_vh (fp16) and g_vf (fp32 stash)
// phase 1: v2 -> g_vh = fp16(v1 + v2)    [logit linearity: b = u·(v1+v2)]
// phase 2: v3 -> d_out (fp32)
// ---------------------------------------------------------------------------
__global__ void squash_kernel(int phase, float* dout) {
    int t = blockIdx.x * blockDim.x + threadIdx.x;
    if (t >= B_ * J_) return;
    const float* sp = g_s + phase * B_ * JO_ + t * O_;
    float sv[16], sq = 0.f;
#pragma unroll
    for (int o = 0; o < 16; o++) { sv[o] = sp[o]; sq += sv[o] * sv[o]; }
    const float scale = sqrtf(sq) / (1.f + sq);
    __half* vh = reinterpret_cast<__half*>(g_vh) + t * O_;
    if (phase == 0) {
#pragma unroll
        for (int o = 0; o < 16; o++) {
            const float v = sv[o] * scale;
            g_vf[t * O_ + o] = v;
            vh[o] = __float2half(v);
        }
    } else if (phase == 1) {
#pragma unroll
        for (int o = 0; o < 16; o++)
            vh[o] = __float2half(g_vf[t * O_ + o] + sv[o] * scale);
    } else {
#pragma unroll
        for (int o = 0; o < 16; o++) dout[t * O_ + o] = sv[o] * scale;
    }
}

// ---------------------------------------------------------------------------
// Fused routing pass (unchanged): 4 p per iteration, prefetched streaming
// uint2 loads; dot via 2 shfl quad-reduce; octet softmax without max-shift
// (logits bounded, fp32 exp safe); no g_b; c*u accumulate via fma.rn.f32x2.
// ---------------------------------------------------------------------------
template <int SLOT>
__global__ __launch_bounds__(256) void route_kernel() {
    const int w     = threadIdx.x >> 5;
    const int lane  = threadIdx.x & 31;
    const int gw    = blockIdx.x * 8 + w;     // 16384 warps
    const int b     = gw >> 9;
    const int pbase = (gw & 511) << 5;        // 32 p per warp

    __shared__ float gbuf[8][40];
    __shared__ float cbuf[8][40];
    __shared__ float red[8][JO_];

    uint2 v2[5];
#pragma unroll
    for (int r = 0; r < 5; r++) {
        const int qq = (4 * (r * 32 + lane)) % 160;
        v2[r] = *(const uint2*)(g_vh + b * JO_ + qq);
    }

    float2 sacc[5][2];
#pragma unroll
    for (int r = 0; r < 5; r++) {
        sacc[r][0] = make_float2(0.f, 0.f);
        sacc[r][1] = make_float2(0.f, 0.f);
    }

    const uint2* up = (const uint2*)(g_uh + ((size_t)b * P_ + pbase) * JO_);

    const int sm_ps = lane >> 3;
    const int k8    = lane & 7;
    const int nj    = (k8 < 2) ? 2 : 1;

    uint2 ucur[5], unxt[5];
#pragma unroll
    for (int r = 0; r < 5; r++) ucur[r] = __ldcs(up + r * 32 + lane);

    for (int it = 0; it < 8; it++) {
        if (it < 7) {
#pragma unroll
            for (int r = 0; r < 5; r++)
                unxt[r] = __ldcs(up + (it + 1) * 160 + r * 32 + lane);
        }

#pragma unroll
        for (int r = 0; r < 5; r++) {
            const __half2* uh2 = (const __half2*)&ucur[r];
            const __half2* vh2 = (const __half2*)&v2[r];
            const __half2 t = __hfma2(uh2[0], vh2[0], __hmul2(uh2[1], vh2[1]));
            float dv = __low2float(t) + __high2float(t);
            dv += __shfl_xor_sync(0xffffffffu, dv, 1);
            dv += __shfl_xor_sync(0xffffffffu, dv, 2);
            if ((lane & 3) == 0) gbuf[w][r * 8 + (lane >> 2)] = dv;
        }
        __syncwarp();

        // softmax over j (no max-shift: |logit| bounded, fp32 exp safe)
        {
            float e[2], sm = 0.f;
#pragma unroll
            for (int i = 0; i < 2; i++) {
                e[i] = (i < nj) ? __expf(gbuf[w][sm_ps * 10 + k8 + i * 8]) : 0.f;
                sm += e[i];
            }
            sm += __shfl_xor_sync(0xffffffffu, sm, 1);
            sm += __shfl_xor_sync(0xffffffffu, sm, 2);
            sm += __shfl_xor_sync(0xffffffffu, sm, 4);
            const float inv = __fdividef(1.f, sm);
#pragma unroll
            for (int i = 0; i < 2; i++)
                if (i < nj) cbuf[w][sm_ps * 10 + k8 + i * 8] = e[i] * inv;
        }
        __syncwarp();

#pragma unroll
        for (int r = 0; r < 5; r++) {
            const float2 c2 = dup2(cbuf[w][r * 8 + (lane >> 2)]);
            const __half2* uh2 = (const __half2*)&ucur[r];
            sacc[r][0] = ffma2(c2, __half22float2(uh2[0]), sacc[r][0]);
            sacc[r][1] = ffma2(c2, __half22float2(uh2[1]), sacc[r][1]);
        }
        __syncwarp();

#pragma unroll
        for (int r = 0; r < 5; r++) ucur[r] = unxt[r];
    }

    for (int i = lane; i < JO_; i += 32) red[w][i] = 0.f;
    __syncwarp();
#pragma unroll
    for (int ph = 0; ph < 4; ph++) {
#pragma unroll
        for (int r = 0; r < 5; r++) {
            const int u = r * 32 + lane;
            if (u / 40 == ph) {
                const int qq = (4 * u) % 160;
                red[w][qq + 0] += sacc[r][0].x;
                red[w][qq + 1] += sacc[r][0].y;
                red[w][qq + 2] += sacc[r][1].x;
                red[w][qq + 3] += sacc[r][1].y;
            }
        }
        __syncwarp();
    }
    __syncthreads();

    if (threadIdx.x < JO_) {
        float s = 0.f;
#pragma unroll
        for (int k = 0; k < 8; k++) s += red[k][threadIdx.x];
        atomicAdd(&g_s[SLOT * B_ * JO_ + b * JO_ + threadIdx.x], s);
    }
}

// ---------------------------------------------------------------------------
extern "C" void kernel_launch(void* const* d_in, const int* in_sizes, int n_in,
                              void* d_out, int out_size) {
    const float* x = (const float*)d_in[0];
    const float* W = (const float*)d_in[1];
    if (n_in >= 2 && in_sizes[0] > in_sizes[1]) {
        x = (const float*)d_in[1];
        W = (const float*)d_in[0];
    }
    float* out = (float*)d_out;

    cudaFuncSetAttribute(pass0_kernel,
                         cudaFuncAttributeMaxDynamicSharedMemorySize,
                         SM_TOTAL_BYTES);

    zero_part_kernel<<<20, 256>>>(0);          // 3 tiny launches: aligns pass0
    zero_part_kernel<<<20, 256>>>(1);          // with the ncu capture slot
    zero_part_kernel<<<20, 256>>>(2);
    pass0_kernel<<<1024, 256, SM_TOTAL_BYTES>>>(x, W);  // u_hat + s1
    squash_kernel<<<2, 160>>>(0, nullptr);     // v1 -> g_vh, g_vf
    route_kernel<1><<<2048, 256>>>();          // logits u·v1 -> s2
    squash_kernel<<<2, 160>>>(1, nullptr);     // g_vh = v1+v2
    route_kernel<2><<<2048, 256>>>();          // logits u·(v1+v2) -> s3
    squash_kernel<<<2, 160>>>(2, out);         // v3 -> out
}